// round 13
// baseline (speedup 1.0000x reference)
#include <cuda_runtime.h>
#include <math.h>

#define Bn   64
#define Mn   10
#define Kn   30
#define Hn   512
#define Nn   128
#define Sn   5
#define NHn  8
#define DHn  64
#define BMn  640
#define BMKn 19200
#define HH   (Hn*Hn)

#define NEG_BIG (-1.0e9f)
#define NEG_INF (-3.402823e38f)

// ---------------- scratch ----------------
__device__ float g_wal  [BMn*Hn];
__device__ float g_sentT[Bn*Hn*Nn];
__device__ float g_WkT  [Sn*HH];
__device__ float g_Wk2T [Sn*HH];
__device__ float g_q1   [Bn*Sn*Mn*Hn];
__device__ float g_t    [Bn*Sn*Mn*NHn*Hn];
__device__ float g_sc1  [Bn*Sn*Mn*NHn*Nn];
__device__ float g_u    [Bn*Sn*Mn*NHn*Hn];
__device__ float g_ctx1 [Bn*Sn*Mn*Hn];
__device__ float g_q2   [Bn*Sn*Mn*Hn];
__device__ float g_r    [Bn*Sn*Mn*NHn*Hn];
__device__ float g_us   [Sn*Hn];
__device__ float g_vs   [Sn*Hn];
__device__ float g_ds   [Sn];
__device__ float g_es   [Sn];
__device__ float g_indp [BMn*Sn];
__device__ float g_margin[BMn*Sn];
__device__ float g_attn [BMn*Sn];
__device__ float g_beff [BMn*Hn];
__device__ float g_fdot [BMKn*Sn];
__device__ int   g_mask_mode;
__device__ float g_weff [BMn*(long)HH];
// ctx pre-split to tf32 hi/lo planes: layout [bm][k(512)][row(32)]
__device__ float g_cth [BMn*16384];
__device__ float g_ctl [BMn*16384];
__device__ float g_pred_s[BMKn*Sn];
__device__ float g_ind_s [Bn*Sn*Mn*2];
__device__ unsigned g_bar_count = 0;
__device__ unsigned g_bar_gen   = 0;

// ---------------- warp helpers ----------------
__device__ __forceinline__ float wsum(float v){
#pragma unroll
    for (int o = 16; o; o >>= 1) v += __shfl_xor_sync(0xffffffffu, v, o);
    return v;
}
__device__ __forceinline__ float wmaxf(float v){
#pragma unroll
    for (int o = 16; o; o >>= 1) v = fmaxf(v, __shfl_xor_sync(0xffffffffu, v, o));
    return v;
}
__device__ __forceinline__ unsigned f2tf32(float x){
    unsigned r; asm("cvt.rna.tf32.f32 %0, %1;" : "=r"(r) : "f"(x)); return r;
}
__device__ __forceinline__ void mma_tf32(float d[4], unsigned a0, unsigned a1,
                                         unsigned a2, unsigned a3,
                                         unsigned b0, unsigned b1){
    asm volatile("mma.sync.aligned.m16n8k8.row.col.f32.tf32.tf32.f32 "
                 "{%0,%1,%2,%3}, {%4,%5,%6,%7}, {%8,%9}, {%0,%1,%2,%3};"
                 : "+f"(d[0]), "+f"(d[1]), "+f"(d[2]), "+f"(d[3])
                 : "r"(a0), "r"(a1), "r"(a2), "r"(a3), "r"(b0), "r"(b1));
}

__device__ __forceinline__ bool mask_padded(const void* m, int idx){
    int mode = g_mask_mode;
    if (mode == 0) return ((const unsigned char*)m)[idx] != 0;
    if (mode == 1) return ((const int*)m)[idx] != 0;
    return ((const float*)m)[idx] != 0.f;
}

// ---------------- software grid barrier ----------------
__device__ __forceinline__ void grid_barrier(){
    __syncthreads();
    if (threadIdx.x == 0){
        __threadfence();
        unsigned gen = atomicAdd(&g_bar_gen, 0u);
        unsigned t = atomicAdd(&g_bar_count, 1u);
        if (t == gridDim.x - 1u){
            atomicExch(&g_bar_count, 0u);
            __threadfence();
            atomicAdd(&g_bar_gen, 1u);
        } else {
            while (atomicAdd(&g_bar_gen, 0u) == gen) __nanosleep(64);
        }
        __threadfence();
    }
    __syncthreads();
}

// ---------------- op functors ----------------
struct OpQ1 {
    const float* Wq; const float* slice;
    static constexpr int ROWS = BMn, KD = Hn;
    __device__ float loadA(int z, int row, int k) const {
        return g_wal[row*Hn + k] + slice[z*Hn + k];
    }
    __device__ float loadB(int z, int k, int n) const { return Wq[(long)z*HH + k*Hn + n]; }
    __device__ void store(int z, int row, int col, float v) const {
        int b = row/Mn, m = row - b*Mn;
        g_q1[((b*Sn + z)*Mn + m)*Hn + col] = v;
    }
};
struct OpT {
    static constexpr int ROWS = BMn, KD = DHn;
    __device__ float loadA(int z, int row, int k) const {
        int s = z >> 3, a = z & 7; int b = row/Mn, m = row - b*Mn;
        return g_q1[((b*Sn + s)*Mn + m)*Hn + a*DHn + k];
    }
    __device__ float loadB(int z, int k, int n) const {
        int s = z >> 3, a = z & 7;
        return g_WkT[(long)s*HH + (a*DHn + k)*Hn + n];
    }
    __device__ void store(int z, int row, int col, float v) const {
        int s = z >> 3, a = z & 7; int b = row/Mn, m = row - b*Mn;
        g_t[(((b*Sn + s)*Mn + m)*NHn + a)*Hn + col] = v;
    }
};
struct OpR {
    static constexpr int ROWS = BMn, KD = DHn;
    __device__ float loadA(int z, int row, int k) const {
        int s = z >> 3, a = z & 7; int b = row/Mn, m = row - b*Mn;
        return g_q2[((b*Sn + s)*Mn + m)*Hn + a*DHn + k];
    }
    __device__ float loadB(int z, int k, int n) const {
        int s = z >> 3, a = z & 7;
        return g_Wk2T[(long)s*HH + (a*DHn + k)*Hn + n];
    }
    __device__ void store(int z, int row, int col, float v) const {
        int s = z >> 3, a = z & 7; int b = row/Mn, m = row - b*Mn;
        g_r[(((b*Sn + s)*Mn + m)*NHn + a)*Hn + col] = v;
    }
};
struct OpSC1 {
    static constexpr int ROWS = 400, KD = Hn;
    __device__ float loadA(int z, int row, int k) const { return g_t[((long)z*400 + row)*Hn + k]; }
    __device__ float loadB(int z, int k, int n) const { return g_sentT[((long)z*Hn + k)*Nn + n]; }
    __device__ void store(int z, int row, int col, float v) const {
        g_sc1[((long)z*400 + row)*Nn + col] = 0.125f * v;
    }
};
struct OpU {
    const float* sent;
    static constexpr int ROWS = 400, KD = Nn;
    __device__ float loadA(int z, int row, int k) const { return g_sc1[((long)z*400 + row)*Nn + k]; }
    __device__ float loadB(int z, int k, int n) const { return sent[((long)z*Nn + k)*Hn + n]; }
    __device__ void store(int z, int row, int col, float v) const {
        g_u[((long)z*400 + row)*Hn + col] = v;
    }
};
struct OpCTX1 {
    const float* Wv;
    static constexpr int ROWS = BMn, KD = Hn;
    __device__ float loadA(int z, int row, int k) const {
        int s = z >> 3, a = z & 7; int b = row/Mn, m = row - b*Mn;
        return g_u[(((b*Sn + s)*Mn + m)*NHn + a)*Hn + k];
    }
    __device__ float loadB(int z, int k, int n) const {
        int s = z >> 3, a = z & 7;
        return Wv[(long)s*HH + k*Hn + a*DHn + n];
    }
    __device__ void store(int z, int row, int col, float v) const {
        int s = z >> 3, a = z & 7; int b = row/Mn, m = row - b*Mn;
        g_ctx1[((b*Sn + s)*Mn + m)*Hn + a*DHn + col] = v;
    }
};
struct OpQ2 {
    const float* Wq2; const float* slice;
    static constexpr int ROWS = BMn, KD = Hn;
    __device__ float loadA(int z, int row, int k) const {
        int b = row/Mn, m = row - b*Mn;
        return g_ctx1[((b*Sn + z)*Mn + m)*Hn + k] + slice[z*Hn + k];
    }
    __device__ float loadB(int z, int k, int n) const { return Wq2[(long)z*HH + k*Hn + n]; }
    __device__ void store(int z, int row, int col, float v) const {
        int b = row/Mn, m = row - b*Mn;
        g_q2[((b*Sn + z)*Mn + m)*Hn + col] = v;
    }
};

// ---------------- tile device functions ----------------
template <class OP>
__device__ void tile_gemm128(const OP& op, int row0, int col0, int z, float* sh, int t){
    float* As = sh;
    float* Bs = sh + 1040;
    const int tr = t >> 5, tc = t & 31;
    float acc[8][4];
#pragma unroll
    for (int i = 0; i < 8; i++)
#pragma unroll
        for (int j = 0; j < 4; j++) acc[i][j] = 0.f;

    for (int k0 = 0; k0 < OP::KD; k0 += 16){
#pragma unroll
        for (int i = 0; i < 4; i++){
            int idx = t + i*256;
            int rr = idx >> 4, kk = idx & 15;
            int row = row0 + rr;
            As[kk*65 + rr] = (row < OP::ROWS) ? op.loadA(z, row, k0 + kk) : 0.f;
        }
#pragma unroll
        for (int i = 0; i < 8; i++){
            int idx = t + i*256;
            int kk = idx >> 7, nn = idx & 127;
            Bs[kk*128 + nn] = op.loadB(z, k0 + kk, col0 + nn);
        }
        __syncthreads();
#pragma unroll
        for (int kk = 0; kk < 16; kk++){
            float4 b = *(const float4*)&Bs[kk*128 + tc*4];
            float a[8];
#pragma unroll
            for (int i = 0; i < 8; i++) a[i] = As[kk*65 + tr*8 + i];
#pragma unroll
            for (int i = 0; i < 8; i++){
                acc[i][0] += a[i]*b.x;
                acc[i][1] += a[i]*b.y;
                acc[i][2] += a[i]*b.z;
                acc[i][3] += a[i]*b.w;
            }
        }
        __syncthreads();
    }
#pragma unroll
    for (int i = 0; i < 8; i++){
        int row = row0 + tr*8 + i;
        if (row >= OP::ROWS) continue;
#pragma unroll
        for (int j = 0; j < 4; j++) op.store(z, row, col0 + tc*4 + j, acc[i][j]);
    }
    __syncthreads();
}

template <class OP>
__device__ void tile_gemm64(const OP& op, int row0, int col0, int z, float* sh, int t){
    float* As = sh;
    float* Bs = sh + 1040;
    const int tr = t >> 5, tc = t & 31;
    float acc[8][2];
#pragma unroll
    for (int i = 0; i < 8; i++){ acc[i][0] = 0.f; acc[i][1] = 0.f; }

    for (int k0 = 0; k0 < OP::KD; k0 += 16){
#pragma unroll
        for (int i = 0; i < 4; i++){
            int idx = t + i*256;
            int rr = idx >> 4, kk = idx & 15;
            int row = row0 + rr;
            As[kk*65 + rr] = (row < OP::ROWS) ? op.loadA(z, row, k0 + kk) : 0.f;
        }
#pragma unroll
        for (int i = 0; i < 4; i++){
            int idx = t + i*256;
            int kk = idx >> 6, nn = idx & 63;
            Bs[kk*64 + nn] = op.loadB(z, k0 + kk, col0 + nn);
        }
        __syncthreads();
#pragma unroll
        for (int kk = 0; kk < 16; kk++){
            float2 b = *(const float2*)&Bs[kk*64 + tc*2];
            float a[8];
#pragma unroll
            for (int i = 0; i < 8; i++) a[i] = As[kk*65 + tr*8 + i];
#pragma unroll
            for (int i = 0; i < 8; i++){
                acc[i][0] += a[i]*b.x;
                acc[i][1] += a[i]*b.y;
            }
        }
        __syncthreads();
    }
#pragma unroll
    for (int i = 0; i < 8; i++){
        int row = row0 + tr*8 + i;
        if (row >= OP::ROWS) continue;
        op.store(z, row, col0 + tc*2, acc[i][0]);
        op.store(z, row, col0 + tc*2 + 1, acc[i][1]);
    }
    __syncthreads();
}

__device__ void tile_transpose(const float* in, float* out, int R, int C,
                               int c0, int r0, float* sh, int t){
    float* tile = sh;
    int tx = t & 31, ty = t >> 5;
#pragma unroll
    for (int i = 0; i < 32; i += 8){
        int r = r0 + ty + i, c = c0 + tx;
        tile[(ty + i)*33 + tx] = (r < R && c < C) ? in[(long)r*C + c] : 0.f;
    }
    __syncthreads();
#pragma unroll
    for (int i = 0; i < 32; i += 8){
        int c = c0 + ty + i, r = r0 + tx;
        if (c < C && r < R) out[(long)c*R + r] = tile[tx*33 + ty + i];
    }
    __syncthreads();
}

__device__ void tile_wal(const float* sent, const int* aidx, int bm, int t){
    int b = bm / Mn;
    int idx = aidx[bm];
    const float* src = sent + ((long)b*Nn + idx)*Hn;
#pragma unroll
    for (int i = 0; i < 2; i++) g_wal[bm*Hn + t + i*256] = src[t + i*256];
}

__device__ void tile_us(const float* Wt, const float* btr, const float* wsh,
                        const float* bsh, const float* wfin, int s, int t){
    int w = t >> 5, lane = t & 31;
    for (int h = w; h < Hn; h += 8){
        const float* wrow = Wt + ((long)s*Hn + h)*Hn;
        float aU = 0.f, aV = 0.f;
        for (int g = lane; g < Hn; g += 32){
            float x = wrow[g];
            aU += x*wsh[g];
            aV += x*wfin[g];
        }
        aU = wsum(aU); aV = wsum(aV);
        if (lane == 0){ g_us[s*Hn + h] = aU; g_vs[s*Hn + h] = aV; }
    }
    if (w == 0){
        float dU = 0.f, dV = 0.f;
        for (int h = lane; h < Hn; h += 32){
            float b = btr[s*Hn + h];
            dU += b*wsh[h];
            dV += b*wfin[h];
        }
        dU = wsum(dU); dV = wsum(dV);
        if (lane == 0){ g_ds[s] = dU + bsh[0]; g_es[s] = dV; }
    }
}

__device__ void tile_maskdetect(const unsigned char* m, float* sh, int t){
    int* si = (int*)sh;
    if (t == 0){ si[0] = 0; si[1] = 0; }
    __syncthreads();
    int c1 = 0, c2 = 0;
    for (int i = t; i < BMKn; i += 256){
        unsigned char v = m[i];
        if (v > 1) c2++;
        else if (v == 1 && (i & 3)) c1++;
    }
    atomicAdd(&si[0], c1);
    atomicAdd(&si[1], c2);
    __syncthreads();
    if (t == 0) g_mask_mode = (si[1] > 0) ? 2 : ((si[0] > 0) ? 0 : 1);
    __syncthreads();
}

__device__ void tile_pred(const float* ctx, float* pred, int bmk, float* sh, int t){
    float* rowv = sh;
#pragma unroll
    for (int i = 0; i < 2; i++) rowv[t + i*256] = ctx[(long)bmk*Hn + t + i*256];
    __syncthreads();
    int w = t >> 5, lane = t & 31;
    for (int d = w; d < 10; d += 8){
        const float* vec = (d < Sn) ? (g_us + d*Hn) : (g_vs + (d - Sn)*Hn);
        float acc = 0.f;
        for (int i = lane; i < Hn; i += 32) acc += rowv[i]*vec[i];
        acc = wsum(acc);
        if (lane == 0){
            if (d < Sn) pred[bmk*Sn + d] = acc + g_ds[d];
            else        g_fdot[bmk*Sn + (d - Sn)] = acc + g_es[d - Sn];
        }
    }
    __syncthreads();
}

__device__ void tile_margin(const float* pred, const void* mask, int bm, int t){
    int w = t >> 5, k = t & 31;
    if (w >= Sn) return;
    bool act = (k < Kn);
    float logit = NEG_BIG;
    if (act){
        float pv = pred[(bm*Kn + k)*Sn + w];
        logit = mask_padded(mask, bm*Kn + k) ? NEG_BIG : pv;
    }
    float mx = wmaxf(act ? logit : NEG_INF);
    float e = act ? expf(logit - mx) : 0.f;
    float sm = wsum(e);
    float lse = logf(sm);
    float conf = act ? (logit - mx - lse) : NEG_INF;
    float v = conf; int idx = k;
#pragma unroll
    for (int o = 16; o; o >>= 1){
        float v2 = __shfl_xor_sync(0xffffffffu, v, o);
        int   i2 = __shfl_xor_sync(0xffffffffu, idx, o);
        if (v2 > v || (v2 == v && i2 < idx)){ v = v2; idx = i2; }
    }
    float c2 = (act && k != idx) ? conf : NEG_INF;
    float v2m = wmaxf(c2);
    if (k == 0) g_margin[bm*Sn + w] = (v - v2m) / (v + v2m);
}

__device__ void tile_sm1(int grp, int t){
    int w = t >> 5, lane = t & 31;
#pragma unroll
    for (int rr = 0; rr < 2; rr++){
        long row = (long)grp*16 + w + rr*8;
        float v[4]; float mx = NEG_INF;
#pragma unroll
        for (int i = 0; i < 4; i++){ v[i] = g_sc1[row*Nn + lane + 32*i]; mx = fmaxf(mx, v[i]); }
        mx = wmaxf(mx);
        float sm = 0.f;
#pragma unroll
        for (int i = 0; i < 4; i++){ v[i] = expf(v[i] - mx); sm += v[i]; }
        sm = wsum(sm);
        float inv = 1.f/sm;
#pragma unroll
        for (int i = 0; i < 4; i++) g_sc1[row*Nn + lane + 32*i] = v[i]*inv;
    }
}

// ---------------- persistent megakernel ----------------
__global__ __launch_bounds__(256, 4) void k_mega(
    const float* __restrict__ sent, const int* __restrict__ aidx,
    const void* __restrict__ mask, const float* __restrict__ ctx,
    const float* __restrict__ Wt, const float* __restrict__ btr,
    const float* __restrict__ wsh, const float* __restrict__ bsh,
    const float* __restrict__ wfin, const float* __restrict__ Wq,
    const float* __restrict__ Wv, const float* __restrict__ Wq2,
    const float* __restrict__ Wk, const float* __restrict__ Wk2,
    const float* __restrict__ sla, const float* __restrict__ sle,
    float* __restrict__ pred)
{
    __shared__ float sh[3088];
    const int t = threadIdx.x;
    const unsigned NB = gridDim.x;

    for (unsigned tt = blockIdx.x; tt < 7302u; tt += NB){
        if (tt < 1280u){
            int cx = tt & 15, cy = (tt >> 4) & 15, z = tt >> 8;
            tile_transpose(Wk + (long)z*HH, g_WkT + (long)z*HH, Hn, Hn, cx*32, cy*32, sh, t);
        } else if (tt < 2560u){
            unsigned u = tt - 1280u;
            int cx = u & 15, cy = (u >> 4) & 15, z = u >> 8;
            tile_transpose(Wk2 + (long)z*HH, g_Wk2T + (long)z*HH, Hn, Hn, cx*32, cy*32, sh, t);
        } else if (tt < 6656u){
            unsigned u = tt - 2560u;
            int cx = u & 15, cy = (u >> 4) & 3, z = u >> 6;
            tile_transpose(sent + (long)z*Nn*Hn, g_sentT + (long)z*Hn*Nn, Nn, Hn, cx*32, cy*32, sh, t);
        } else if (tt < 7296u){
            tile_wal(sent, aidx, (int)(tt - 6656u), t);
        } else if (tt < 7301u){
            tile_us(Wt, btr, wsh, bsh, wfin, (int)(tt - 7296u), t);
        } else {
            tile_maskdetect((const unsigned char*)mask, sh, t);
        }
    }
    grid_barrier();

    {
        OpQ1 op{Wq, sla};
        for (unsigned tt = blockIdx.x; tt < 19400u; tt += NB){
            if (tt < 19200u) tile_pred(ctx, pred, (int)tt, sh, t);
            else {
                unsigned q = tt - 19200u;
                tile_gemm128(op, (int)(q % 10u)*64, (int)((q/10u) % 4u)*128, (int)(q/40u), sh, t);
            }
        }
    }
    grid_barrier();

    {
        OpT op{};
        for (unsigned tt = blockIdx.x; tt < 2240u; tt += NB){
            if (tt < 640u) tile_margin(pred, mask, (int)tt, t);
            else {
                unsigned q = tt - 640u;
                tile_gemm128(op, (int)(q % 10u)*64, (int)((q/10u) % 4u)*128, (int)(q/40u), sh, t);
            }
        }
    }
    grid_barrier();

    {
        OpSC1 op{};
        for (unsigned tt = blockIdx.x; tt < 448u; tt += NB)
            tile_gemm128(op, (int)(tt % 7u)*64, 0, (int)(tt/7u), sh, t);
    }
    grid_barrier();

    for (unsigned tt = blockIdx.x; tt < 1600u; tt += NB) tile_sm1((int)tt, t);
    grid_barrier();

    {
        OpU op{sent};
        for (unsigned tt = blockIdx.x; tt < 1792u; tt += NB)
            tile_gemm128(op, (int)(tt % 7u)*64, (int)((tt/7u) % 4u)*128, (int)(tt/28u), sh, t);
    }
    grid_barrier();

    {
        OpCTX1 op{Wv};
        for (unsigned tt = blockIdx.x; tt < 400u; tt += NB)
            tile_gemm64(op, (int)(tt % 10u)*64, 0, (int)(tt/10u), sh, t);
    }
    grid_barrier();

    {
        OpQ2 op{Wq2, sle};
        for (unsigned tt = blockIdx.x; tt < 200u; tt += NB)
            tile_gemm128(op, (int)(tt % 10u)*64, (int)((tt/10u) % 4u)*128, (int)(tt/40u), sh, t);
    }
    grid_barrier();

    {
        OpR op{};
        for (unsigned tt = blockIdx.x; tt < 1600u; tt += NB)
            tile_gemm128(op, (int)(tt % 10u)*64, (int)((tt/10u) % 4u)*128, (int)(tt/40u), sh, t);
    }
}

// ---------------- stage2 ----------------
#define CP 520
__global__ void k_stage2(const float* __restrict__ ctx, const void* __restrict__ mask,
                         const float* __restrict__ Wind, const float* __restrict__ bind,
                         float* __restrict__ ind_out){
    extern __shared__ float smem[];
    float* ctx_sh   = smem;
    float* r_sh     = ctx_sh + Kn*CP;
    float* alias_sh = r_sh + NHn*CP;
    float* ew_sh    = alias_sh + Hn;
    float* red      = ew_sh + NHn*32;

    int blk = blockIdx.x;
    int m = blk % Mn; int bs = blk / Mn; int s = bs % Sn; int b = bs / Sn;
    int bm = b*Mn + m;
    int tid = threadIdx.x;
    for (int i = tid; i < Kn*Hn; i += 256){
        int r = i >> 9, h = i & 511;
        ctx_sh[r*CP + h] = ctx[((long)bm*Kn + r)*Hn + h];
    }
    for (int i = tid; i < NHn*Hn; i += 256){
        int a = i >> 9, h = i & 511;
        r_sh[a*CP + h] = g_r[((long)blk*NHn + a)*Hn + h];
    }
    __syncthreads();

    int a = tid >> 5, k = tid & 31;
    {
        bool act = (k < Kn);
        float acc = 0.f;
        if (act){
            const float4* cp = reinterpret_cast<const float4*>(ctx_sh + k*CP);
            const float4* rp = reinterpret_cast<const float4*>(r_sh + a*CP);
            for (int h4 = 0; h4 < Hn/4; h4++){
                float4 c = cp[h4], rr = rp[h4];
                acc += c.x*rr.x + c.y*rr.y + c.z*rr.z + c.w*rr.w;
            }
        }
        float x = NEG_BIG;
        if (act) x = mask_padded(mask, bm*Kn + k) ? NEG_BIG : acc*0.125f;
        float mx = wmaxf(act ? x : NEG_INF);
        float e = act ? expf(x - mx) : 0.f;
        float sv = wsum(e);
        if (act) ew_sh[a*32 + k] = e/sv;
    }
    __syncthreads();
    for (int g = tid; g < Hn; g += 256){
        int ah = g >> 6;
        float acc = 0.f;
#pragma unroll
        for (int kk = 0; kk < Kn; kk++) acc += ew_sh[ah*32 + kk]*ctx_sh[kk*CP + g];
        alias_sh[g] = acc;
    }
    __syncthreads();
    float p0 = 0.f, p1 = 0.f;
    for (int g = tid; g < Hn; g += 256){
        float av = alias_sh[g];
        p0 += av*Wind[(s*Hn + g)*2 + 0];
        p1 += av*Wind[(s*Hn + g)*2 + 1];
    }
    p0 = wsum(p0); p1 = wsum(p1);
    if ((tid & 31) == 0){ red[(tid >> 5)*2] = p0; red[(tid >> 5)*2 + 1] = p1; }
    __syncthreads();
    if (tid == 0){
        float i0 = 0.f, i1 = 0.f;
        for (int wv = 0; wv < 8; wv++){ i0 += red[wv*2]; i1 += red[wv*2 + 1]; }
        i0 += bind[s*2 + 0]; i1 += bind[s*2 + 1];
        ind_out[blk*2 + 0] = i0;
        ind_out[blk*2 + 1] = i1;
        float mx = fmaxf(i0, i1);
        float lse = mx + logf(expf(i0 - mx) + expf(i1 - mx));
        g_indp[bm*Sn + s] = i1 - lse;
    }
}

__global__ void k_attn_beff(const float* __restrict__ btr){
    __shared__ float at[Sn];
    int bm = blockIdx.x, t = threadIdx.x;
    if (t < 32){
        int s = t;
        bool act = (s < Sn);
        float x = act ? (g_indp[bm*Sn + s] + g_margin[bm*Sn + s])*4.0f : NEG_INF;
        float mx = wmaxf(x);
        float e = act ? expf(x - mx) : 0.f;
        float sm = wsum(e);
        if (act){ float v = e/sm; g_attn[bm*Sn + s] = v; at[s] = v; }
    }
    __syncthreads();
    float acc = 0.f;
#pragma unroll
    for (int s = 0; s < Sn; s++) acc += at[s]*btr[s*Hn + t];
    g_beff[bm*Hn + t] = acc;
}

__global__ void k_finalv(const float* __restrict__ bfin, float* __restrict__ out){
    int i = blockIdx.x*256 + threadIdx.x;
    if (i >= BMKn) return;
    int bm = i / Kn;
    float acc = bfin[0];
#pragma unroll
    for (int s = 0; s < Sn; s++) acc += g_attn[bm*Sn + s]*g_fdot[i*Sn + s];
    out[i] = acc;
}

// ---------------- ctx -> tf32 hi/lo planes [bm][k][row] ----------------
#define CSP 513
__global__ void k_ctxsplit(const float* __restrict__ ctx){
    extern __shared__ float shs[];   // 30 x 513
    int bm = blockIdx.x, t = threadIdx.x;
    const float* src = ctx + (long)bm*Kn*Hn;
    for (int i = t; i < Kn*Hn; i += 256){
        int r = i >> 9, c = i & 511;
        shs[r*CSP + c] = src[i];
    }
    __syncthreads();
    float* oh = g_cth + (long)bm*16384;
    float* ol = g_ctl + (long)bm*16384;
    for (int idx = t; idx < 16384; idx += 256){
        int k = idx >> 5, r = idx & 31;
        float x = (r < Kn) ? shs[r*CSP + k] : 0.f;
        float hi = __uint_as_float(f2tf32(x));
        float lo = __uint_as_float(f2tf32(x - hi));
        oh[idx] = hi;
        ol[idx] = lo;
    }
}

// ---------------- REW phase 1 (R11 measured-best): Weff pre-rounded to tf32 ----------
__global__ __launch_bounds__(256) void k_weff(const float* __restrict__ Wt){
    __shared__ float at[BMn*Sn];
    const int k0 = blockIdx.x*32, n0 = blockIdx.y*64;
    const int t = threadIdx.x;
    for (int i = t; i < BMn*Sn; i += 256) at[i] = g_attn[i];
    const int kk = t >> 3, cg = t & 7;
    float w[Sn][8];
#pragma unroll
    for (int s = 0; s < Sn; s++){
        *(float4*)&w[s][0] = *(const float4*)&Wt[((long)s*Hn + k0 + kk)*Hn + n0 + cg*8];
        *(float4*)&w[s][4] = *(const float4*)&Wt[((long)s*Hn + k0 + kk)*Hn + n0 + cg*8 + 4];
    }
    __syncthreads();
    float* dst0 = g_weff + (long)(k0 + kk)*Hn + n0 + cg*8;
    for (int bm = 0; bm < BMn; bm++){
        float a0 = at[bm*Sn+0], a1 = at[bm*Sn+1], a2 = at[bm*Sn+2],
              a3 = at[bm*Sn+3], a4 = at[bm*Sn+4];
        float o[8];
#pragma unroll
        for (int j = 0; j < 8; j++){
            float v = a0*w[0][j] + a1*w[1][j] + a2*w[2][j] + a3*w[3][j] + a4*w[4][j];
            o[j] = __uint_as_float(f2tf32(v));   // pre-round for tf32 MMA consume
        }
        float* dst = dst0 + (long)bm*HH;
        *(float4*)dst       = *(float4*)&o[0];
        *(float4*)(dst + 4) = *(float4*)&o[4];
    }
}

// ---------------- REW phase 2: tf32 2-pass tensor GEMM (pure LDS+MMA loop) ----------
// D = Ah*B + Al*B (exact in A; error = tf32 rounding of B only).
#define KC 8
__global__ __launch_bounds__(256) void k_rewT2(float* __restrict__ outp){
    __shared__ float Ah[KC][40];
    __shared__ float Al[KC][40];
    __shared__ float Bs[KC][520];

    const int bm = blockIdx.x;
    const int t = threadIdx.x;
    const int w = t >> 5, lane = t & 31;

    const float* Ahg = g_cth + (long)bm*16384;
    const float* Alg = g_ctl + (long)bm*16384;
    const float* Bg  = g_weff + (long)bm*HH;

    float d[2][8][4];
#pragma unroll
    for (int m = 0; m < 2; m++)
#pragma unroll
        for (int nt = 0; nt < 8; nt++)
#pragma unroll
            for (int r = 0; r < 4; r++) d[m][nt][r] = 0.f;

    const int akk = t >> 5, arow = t & 31;

    for (int k0 = 0; k0 < Hn; k0 += KC){
        // A: coalesced plane loads (one hi + one lo per thread)
        Ah[akk][arow] = Ahg[(k0 + akk)*32 + arow];
        Al[akk][arow] = Alg[(k0 + akk)*32 + arow];
        // B: 8x512 floats (already tf32-rounded), 4 float4 per thread
#pragma unroll
        for (int p = 0; p < 4; p++){
            int idx = t + p*256;
            int kk = idx >> 7, c4 = (idx & 127) << 2;
            *(float4*)&Bs[kk][c4] = *(const float4*)&Bg[(long)(k0 + kk)*Hn + c4];
        }
        __syncthreads();

        const int ar = lane >> 2, ac = lane & 3;
        unsigned ah[2][4], al[2][4];
#pragma unroll
        for (int m = 0; m < 2; m++){
            int rb = ar + m*16;
            ah[m][0] = __float_as_uint(Ah[ac][rb]);
            ah[m][1] = __float_as_uint(Ah[ac][rb + 8]);
            ah[m][2] = __float_as_uint(Ah[ac + 4][rb]);
            ah[m][3] = __float_as_uint(Ah[ac + 4][rb + 8]);
            al[m][0] = __float_as_uint(Al[ac][rb]);
            al[m][1] = __float_as_uint(Al[ac][rb + 8]);
            al[m][2] = __float_as_uint(Al[ac + 4][rb]);
            al[m][3] = __float_as_uint(Al[ac + 4][rb + 8]);
        }
#pragma unroll
        for (int nt = 0; nt < 8; nt++){
            int bn = w*64 + nt*8 + (lane >> 2);
            int bk = lane & 3;
            unsigned b0 = __float_as_uint(Bs[bk][bn]);
            unsigned b1 = __float_as_uint(Bs[bk + 4][bn]);
#pragma unroll
            for (int m = 0; m < 2; m++){
                mma_tf32(d[m][nt], ah[m][0], ah[m][1], ah[m][2], ah[m][3], b0, b1);
                mma_tf32(d[m][nt], al[m][0], al[m][1], al[m][2], al[m][3], b0, b1);
            }
        }
        __syncthreads();
    }

    const int er = lane >> 2, ec = (lane & 3)*2;
#pragma unroll
    for (int nt = 0; nt < 8; nt++){
        int col = w*64 + nt*8 + ec;
        float2 be = *(const float2*)&g_beff[bm*Hn + col];
#pragma unroll
        for (int m = 0; m < 2; m++){
            int r0 = er + m*16;
            int r1 = r0 + 8;
            if (r0 < Kn){
                float2 v = {d[m][nt][0] + be.x, d[m][nt][1] + be.y};
                *(float2*)&outp[((long)(bm*Kn + r0))*Hn + col] = v;
            }
            if (r1 < Kn){
                float2 v = {d[m][nt][2] + be.x, d[m][nt][3] + be.y};
                *(float2*)&outp[((long)(bm*Kn + r1))*Hn + col] = v;
            }
        }
    }
}

// ---------------- host launcher ----------------
extern "C" void kernel_launch(void* const* d_in, const int* in_sizes, int n_in,
                              void* d_out, int out_size){
    const float* ctx  = (const float*)d_in[0];
    const float* sent = (const float*)d_in[1];
    const int*   aidx = (const int*)d_in[2];
    const void*  mask = (const void*)d_in[3];
    const float* Wtr  = (const float*)d_in[4];
    const float* btr  = (const float*)d_in[5];
    const float* Wind = (const float*)d_in[6];
    const float* bind = (const float*)d_in[7];
    const float* Wq   = (const float*)d_in[8];
    const float* Wk   = (const float*)d_in[9];
    const float* Wv   = (const float*)d_in[10];
    const float* Wq2  = (const float*)d_in[11];
    const float* Wk2  = (const float*)d_in[12];
    const float* sla  = (const float*)d_in[13];
    const float* sle  = (const float*)d_in[14];
    const float* wsh  = (const float*)d_in[15];
    const float* bsh  = (const float*)d_in[16];
    const float* wfin = (const float*)d_in[17];
    const float* bfin = (const float*)d_in[18];
    float* out = (float*)d_out;

    void* tmp;
    cudaGetSymbolAddress(&tmp, g_pred_s); float* pred_s = (float*)tmp;
    cudaGetSymbolAddress(&tmp, g_ind_s);  float* ind_s  = (float*)tmp;

    const bool big_out = (out_size >= (BMKn + BMKn*Hn + BMKn*Sn + Bn*Sn*Mn*2));
    float *p_final = out;
    float *p_rew  = big_out ? out + BMKn : nullptr;
    float *p_pred = big_out ? out + BMKn + BMKn*Hn : pred_s;
    float *p_ind  = big_out ? out + BMKn + BMKn*Hn + BMKn*Sn : ind_s;

    cudaFuncSetAttribute(k_stage2, cudaFuncAttributeMaxDynamicSharedMemorySize, 90*1024);
    cudaFuncSetAttribute(k_ctxsplit, cudaFuncAttributeMaxDynamicSharedMemorySize, 64*1024);

    int dev = 0; cudaGetDevice(&dev);
    int sms = 148;
    cudaDeviceGetAttribute(&sms, cudaDevAttrMultiProcessorCount, dev);
    int nb = 0;
    cudaOccupancyMaxActiveBlocksPerMultiprocessor(&nb, k_mega, 256, 0);
    if (nb < 4) nb = 4;
    int grid = nb * sms;

    if (big_out){
        size_t smc = (size_t)Kn*CSP*sizeof(float);
        k_ctxsplit<<<BMn, 256, smc>>>(ctx);
    }

    k_mega<<<grid, 256>>>(sent, aidx, mask, ctx, Wtr, btr, wsh, bsh, wfin,
                          Wq, Wv, Wq2, Wk, Wk2, sla, sle, p_pred);

    size_t sm2 = (size_t)(Kn*CP + NHn*CP + Hn + NHn*32 + 16)*sizeof(float);
    k_stage2<<<Bn*Sn*Mn, 256, sm2>>>(ctx, mask, Wind, bind, p_ind);

    k_attn_beff<<<BMn, 512>>>(btr);

    if (big_out){
        k_weff<<<dim3(16, 8), 256>>>(Wtr);
        k_rewT2<<<BMn, 256>>>(p_rew);
    }
    k_finalv<<<(BMKn + 255)/256, 256>>>(bfin, p_final);
}

// round 14
// speedup vs baseline: 1.0190x; 1.0190x over previous
#include <cuda_runtime.h>
#include <math.h>

#define Bn   64
#define Mn   10
#define Kn   30
#define Hn   512
#define Nn   128
#define Sn   5
#define NHn  8
#define DHn  64
#define BMn  640
#define BMKn 19200
#define HH   (Hn*Hn)

#define NEG_BIG (-1.0e9f)
#define NEG_INF (-3.402823e38f)

// ---------------- scratch ----------------
__device__ float g_wal  [BMn*Hn];
__device__ float g_sentT[Bn*Hn*Nn];
__device__ float g_WkT  [Sn*HH];
__device__ float g_Wk2T [Sn*HH];
__device__ float g_q1   [Bn*Sn*Mn*Hn];
__device__ float g_t    [Bn*Sn*Mn*NHn*Hn];
__device__ float g_sc1  [Bn*Sn*Mn*NHn*Nn];
__device__ float g_u    [Bn*Sn*Mn*NHn*Hn];
__device__ float g_ctx1 [Bn*Sn*Mn*Hn];
__device__ float g_q2   [Bn*Sn*Mn*Hn];
__device__ float g_r    [Bn*Sn*Mn*NHn*Hn];
__device__ float g_us   [Sn*Hn];
__device__ float g_vs   [Sn*Hn];
__device__ float g_ds   [Sn];
__device__ float g_es   [Sn];
__device__ float g_indp [BMn*Sn];
__device__ float g_margin[BMn*Sn];
__device__ float g_attn [BMn*Sn];
__device__ float g_beff [BMn*Hn];
__device__ float g_fdot [BMKn*Sn];
__device__ int   g_mask_mode;
__device__ float g_weff [BMn*(long)HH];
__device__ float g_pred_s[BMKn*Sn];
__device__ float g_ind_s [Bn*Sn*Mn*2];
__device__ unsigned g_bar_count = 0;
__device__ unsigned g_bar_gen   = 0;

// ---------------- warp helpers ----------------
__device__ __forceinline__ float wsum(float v){
#pragma unroll
    for (int o = 16; o; o >>= 1) v += __shfl_xor_sync(0xffffffffu, v, o);
    return v;
}
__device__ __forceinline__ float wmaxf(float v){
#pragma unroll
    for (int o = 16; o; o >>= 1) v = fmaxf(v, __shfl_xor_sync(0xffffffffu, v, o));
    return v;
}

__device__ __forceinline__ bool mask_padded(const void* m, int idx){
    int mode = g_mask_mode;
    if (mode == 0) return ((const unsigned char*)m)[idx] != 0;
    if (mode == 1) return ((const int*)m)[idx] != 0;
    return ((const float*)m)[idx] != 0.f;
}

// ---------------- software grid barrier ----------------
__device__ __forceinline__ void grid_barrier(){
    __syncthreads();
    if (threadIdx.x == 0){
        __threadfence();
        unsigned gen = atomicAdd(&g_bar_gen, 0u);
        unsigned t = atomicAdd(&g_bar_count, 1u);
        if (t == gridDim.x - 1u){
            atomicExch(&g_bar_count, 0u);
            __threadfence();
            atomicAdd(&g_bar_gen, 1u);
        } else {
            while (atomicAdd(&g_bar_gen, 0u) == gen) __nanosleep(64);
        }
        __threadfence();
    }
    __syncthreads();
}

// ---------------- op functors ----------------
struct OpQ1 {
    const float* Wq; const float* slice;
    static constexpr int ROWS = BMn, KD = Hn;
    __device__ float loadA(int z, int row, int k) const {
        return g_wal[row*Hn + k] + slice[z*Hn + k];
    }
    __device__ float loadB(int z, int k, int n) const { return Wq[(long)z*HH + k*Hn + n]; }
    __device__ void store(int z, int row, int col, float v) const {
        int b = row/Mn, m = row - b*Mn;
        g_q1[((b*Sn + z)*Mn + m)*Hn + col] = v;
    }
};
struct OpT {
    static constexpr int ROWS = BMn, KD = DHn;
    __device__ float loadA(int z, int row, int k) const {
        int s = z >> 3, a = z & 7; int b = row/Mn, m = row - b*Mn;
        return g_q1[((b*Sn + s)*Mn + m)*Hn + a*DHn + k];
    }
    __device__ float loadB(int z, int k, int n) const {
        int s = z >> 3, a = z & 7;
        return g_WkT[(long)s*HH + (a*DHn + k)*Hn + n];
    }
    __device__ void store(int z, int row, int col, float v) const {
        int s = z >> 3, a = z & 7; int b = row/Mn, m = row - b*Mn;
        g_t[(((b*Sn + s)*Mn + m)*NHn + a)*Hn + col] = v;
    }
};
struct OpR {
    static constexpr int ROWS = BMn, KD = DHn;
    __device__ float loadA(int z, int row, int k) const {
        int s = z >> 3, a = z & 7; int b = row/Mn, m = row - b*Mn;
        return g_q2[((b*Sn + s)*Mn + m)*Hn + a*DHn + k];
    }
    __device__ float loadB(int z, int k, int n) const {
        int s = z >> 3, a = z & 7;
        return g_Wk2T[(long)s*HH + (a*DHn + k)*Hn + n];
    }
    __device__ void store(int z, int row, int col, float v) const {
        int s = z >> 3, a = z & 7; int b = row/Mn, m = row - b*Mn;
        g_r[(((b*Sn + s)*Mn + m)*NHn + a)*Hn + col] = v;
    }
};
struct OpSC1 {
    static constexpr int ROWS = 400, KD = Hn;
    __device__ float loadA(int z, int row, int k) const { return g_t[((long)z*400 + row)*Hn + k]; }
    __device__ float loadB(int z, int k, int n) const { return g_sentT[((long)z*Hn + k)*Nn + n]; }
    __device__ void store(int z, int row, int col, float v) const {
        g_sc1[((long)z*400 + row)*Nn + col] = 0.125f * v;
    }
};
struct OpU {
    const float* sent;
    static constexpr int ROWS = 400, KD = Nn;
    __device__ float loadA(int z, int row, int k) const { return g_sc1[((long)z*400 + row)*Nn + k]; }
    __device__ float loadB(int z, int k, int n) const { return sent[((long)z*Nn + k)*Hn + n]; }
    __device__ void store(int z, int row, int col, float v) const {
        g_u[((long)z*400 + row)*Hn + col] = v;
    }
};
struct OpCTX1 {
    const float* Wv;
    static constexpr int ROWS = BMn, KD = Hn;
    __device__ float loadA(int z, int row, int k) const {
        int s = z >> 3, a = z & 7; int b = row/Mn, m = row - b*Mn;
        return g_u[(((b*Sn + s)*Mn + m)*NHn + a)*Hn + k];
    }
    __device__ float loadB(int z, int k, int n) const {
        int s = z >> 3, a = z & 7;
        return Wv[(long)s*HH + k*Hn + a*DHn + n];
    }
    __device__ void store(int z, int row, int col, float v) const {
        int s = z >> 3, a = z & 7; int b = row/Mn, m = row - b*Mn;
        g_ctx1[((b*Sn + s)*Mn + m)*Hn + a*DHn + col] = v;
    }
};
struct OpQ2 {
    const float* Wq2; const float* slice;
    static constexpr int ROWS = BMn, KD = Hn;
    __device__ float loadA(int z, int row, int k) const {
        int b = row/Mn, m = row - b*Mn;
        return g_ctx1[((b*Sn + z)*Mn + m)*Hn + k] + slice[z*Hn + k];
    }
    __device__ float loadB(int z, int k, int n) const { return Wq2[(long)z*HH + k*Hn + n]; }
    __device__ void store(int z, int row, int col, float v) const {
        int b = row/Mn, m = row - b*Mn;
        g_q2[((b*Sn + z)*Mn + m)*Hn + col] = v;
    }
};

// ---------------- tile device functions ----------------
template <class OP>
__device__ void tile_gemm128(const OP& op, int row0, int col0, int z, float* sh, int t){
    float* As = sh;
    float* Bs = sh + 1040;
    const int tr = t >> 5, tc = t & 31;
    float acc[8][4];
#pragma unroll
    for (int i = 0; i < 8; i++)
#pragma unroll
        for (int j = 0; j < 4; j++) acc[i][j] = 0.f;

    for (int k0 = 0; k0 < OP::KD; k0 += 16){
#pragma unroll
        for (int i = 0; i < 4; i++){
            int idx = t + i*256;
            int rr = idx >> 4, kk = idx & 15;
            int row = row0 + rr;
            As[kk*65 + rr] = (row < OP::ROWS) ? op.loadA(z, row, k0 + kk) : 0.f;
        }
#pragma unroll
        for (int i = 0; i < 8; i++){
            int idx = t + i*256;
            int kk = idx >> 7, nn = idx & 127;
            Bs[kk*128 + nn] = op.loadB(z, k0 + kk, col0 + nn);
        }
        __syncthreads();
#pragma unroll
        for (int kk = 0; kk < 16; kk++){
            float4 b = *(const float4*)&Bs[kk*128 + tc*4];
            float a[8];
#pragma unroll
            for (int i = 0; i < 8; i++) a[i] = As[kk*65 + tr*8 + i];
#pragma unroll
            for (int i = 0; i < 8; i++){
                acc[i][0] += a[i]*b.x;
                acc[i][1] += a[i]*b.y;
                acc[i][2] += a[i]*b.z;
                acc[i][3] += a[i]*b.w;
            }
        }
        __syncthreads();
    }
#pragma unroll
    for (int i = 0; i < 8; i++){
        int row = row0 + tr*8 + i;
        if (row >= OP::ROWS) continue;
#pragma unroll
        for (int j = 0; j < 4; j++) op.store(z, row, col0 + tc*4 + j, acc[i][j]);
    }
    __syncthreads();
}

template <class OP>
__device__ void tile_gemm64(const OP& op, int row0, int col0, int z, float* sh, int t){
    float* As = sh;
    float* Bs = sh + 1040;
    const int tr = t >> 5, tc = t & 31;
    float acc[8][2];
#pragma unroll
    for (int i = 0; i < 8; i++){ acc[i][0] = 0.f; acc[i][1] = 0.f; }

    for (int k0 = 0; k0 < OP::KD; k0 += 16){
#pragma unroll
        for (int i = 0; i < 4; i++){
            int idx = t + i*256;
            int rr = idx >> 4, kk = idx & 15;
            int row = row0 + rr;
            As[kk*65 + rr] = (row < OP::ROWS) ? op.loadA(z, row, k0 + kk) : 0.f;
        }
#pragma unroll
        for (int i = 0; i < 4; i++){
            int idx = t + i*256;
            int kk = idx >> 6, nn = idx & 63;
            Bs[kk*64 + nn] = op.loadB(z, k0 + kk, col0 + nn);
        }
        __syncthreads();
#pragma unroll
        for (int kk = 0; kk < 16; kk++){
            float2 b = *(const float2*)&Bs[kk*64 + tc*2];
            float a[8];
#pragma unroll
            for (int i = 0; i < 8; i++) a[i] = As[kk*65 + tr*8 + i];
#pragma unroll
            for (int i = 0; i < 8; i++){
                acc[i][0] += a[i]*b.x;
                acc[i][1] += a[i]*b.y;
            }
        }
        __syncthreads();
    }
#pragma unroll
    for (int i = 0; i < 8; i++){
        int row = row0 + tr*8 + i;
        if (row >= OP::ROWS) continue;
        op.store(z, row, col0 + tc*2, acc[i][0]);
        op.store(z, row, col0 + tc*2 + 1, acc[i][1]);
    }
    __syncthreads();
}

__device__ void tile_transpose(const float* in, float* out, int R, int C,
                               int c0, int r0, float* sh, int t){
    float* tile = sh;
    int tx = t & 31, ty = t >> 5;
#pragma unroll
    for (int i = 0; i < 32; i += 8){
        int r = r0 + ty + i, c = c0 + tx;
        tile[(ty + i)*33 + tx] = (r < R && c < C) ? in[(long)r*C + c] : 0.f;
    }
    __syncthreads();
#pragma unroll
    for (int i = 0; i < 32; i += 8){
        int c = c0 + ty + i, r = r0 + tx;
        if (c < C && r < R) out[(long)c*R + r] = tile[tx*33 + ty + i];
    }
    __syncthreads();
}

__device__ void tile_wal(const float* sent, const int* aidx, int bm, int t){
    int b = bm / Mn;
    int idx = aidx[bm];
    const float* src = sent + ((long)b*Nn + idx)*Hn;
#pragma unroll
    for (int i = 0; i < 2; i++) g_wal[bm*Hn + t + i*256] = src[t + i*256];
}

__device__ void tile_us(const float* Wt, const float* btr, const float* wsh,
                        const float* bsh, const float* wfin, int s, int t){
    int w = t >> 5, lane = t & 31;
    for (int h = w; h < Hn; h += 8){
        const float* wrow = Wt + ((long)s*Hn + h)*Hn;
        float aU = 0.f, aV = 0.f;
        for (int g = lane; g < Hn; g += 32){
            float x = wrow[g];
            aU += x*wsh[g];
            aV += x*wfin[g];
        }
        aU = wsum(aU); aV = wsum(aV);
        if (lane == 0){ g_us[s*Hn + h] = aU; g_vs[s*Hn + h] = aV; }
    }
    if (w == 0){
        float dU = 0.f, dV = 0.f;
        for (int h = lane; h < Hn; h += 32){
            float b = btr[s*Hn + h];
            dU += b*wsh[h];
            dV += b*wfin[h];
        }
        dU = wsum(dU); dV = wsum(dV);
        if (lane == 0){ g_ds[s] = dU + bsh[0]; g_es[s] = dV; }
    }
}

__device__ void tile_maskdetect(const unsigned char* m, float* sh, int t){
    int* si = (int*)sh;
    if (t == 0){ si[0] = 0; si[1] = 0; }
    __syncthreads();
    int c1 = 0, c2 = 0;
    for (int i = t; i < BMKn; i += 256){
        unsigned char v = m[i];
        if (v > 1) c2++;
        else if (v == 1 && (i & 3)) c1++;
    }
    atomicAdd(&si[0], c1);
    atomicAdd(&si[1], c2);
    __syncthreads();
    if (t == 0) g_mask_mode = (si[1] > 0) ? 2 : ((si[0] > 0) ? 0 : 1);
    __syncthreads();
}

// batched pred: 256 bmk rows per tile; basis [us|vs] staged in smem (5120 floats)
__device__ void tile_predg(const float* ctx, float* pred, int row0, float* sh, int t){
    for (int i = t; i < 5120; i += 256)
        sh[i] = (i < 2560) ? g_us[i] : g_vs[i - 2560];
    __syncthreads();
    int w = t >> 5, lane = t & 31;
    int rbase = row0 + w*32;
#pragma unroll 1
    for (int i = 0; i < 32; i++){
        int r = rbase + i;
        const float* cp = ctx + (long)r*Hn;
        float a[16];
#pragma unroll
        for (int j = 0; j < 16; j++) a[j] = cp[lane + 32*j];
#pragma unroll
        for (int d = 0; d < 10; d++){
            const float* vv = sh + d*512;
            float acc = 0.f;
#pragma unroll
            for (int j = 0; j < 16; j++) acc += a[j]*vv[lane + 32*j];
            acc = wsum(acc);
            if (lane == 0){
                if (d < Sn) pred[r*Sn + d] = acc + g_ds[d];
                else        g_fdot[r*Sn + (d - Sn)] = acc + g_es[d - Sn];
            }
        }
    }
    __syncthreads();
}

__device__ void tile_margin(const float* pred, const void* mask, int bm, int t){
    int w = t >> 5, k = t & 31;
    if (w >= Sn) return;
    bool act = (k < Kn);
    float logit = NEG_BIG;
    if (act){
        float pv = pred[(bm*Kn + k)*Sn + w];
        logit = mask_padded(mask, bm*Kn + k) ? NEG_BIG : pv;
    }
    float mx = wmaxf(act ? logit : NEG_INF);
    float e = act ? expf(logit - mx) : 0.f;
    float sm = wsum(e);
    float lse = logf(sm);
    float conf = act ? (logit - mx - lse) : NEG_INF;
    float v = conf; int idx = k;
#pragma unroll
    for (int o = 16; o; o >>= 1){
        float v2 = __shfl_xor_sync(0xffffffffu, v, o);
        int   i2 = __shfl_xor_sync(0xffffffffu, idx, o);
        if (v2 > v || (v2 == v && i2 < idx)){ v = v2; idx = i2; }
    }
    float c2 = (act && k != idx) ? conf : NEG_INF;
    float v2m = wmaxf(c2);
    if (k == 0) g_margin[bm*Sn + w] = (v - v2m) / (v + v2m);
}

__device__ void tile_sm1(int grp, int t){
    int w = t >> 5, lane = t & 31;
#pragma unroll
    for (int rr = 0; rr < 2; rr++){
        long row = (long)grp*16 + w + rr*8;
        float v[4]; float mx = NEG_INF;
#pragma unroll
        for (int i = 0; i < 4; i++){ v[i] = g_sc1[row*Nn + lane + 32*i]; mx = fmaxf(mx, v[i]); }
        mx = wmaxf(mx);
        float sm = 0.f;
#pragma unroll
        for (int i = 0; i < 4; i++){ v[i] = expf(v[i] - mx); sm += v[i]; }
        sm = wsum(sm);
        float inv = 1.f/sm;
#pragma unroll
        for (int i = 0; i < 4; i++) g_sc1[row*Nn + lane + 32*i] = v[i]*inv;
    }
}

// ---------------- persistent megakernel ----------------
__global__ __launch_bounds__(256, 4) void k_mega(
    const float* __restrict__ sent, const int* __restrict__ aidx,
    const void* __restrict__ mask, const float* __restrict__ ctx,
    const float* __restrict__ Wt, const float* __restrict__ btr,
    const float* __restrict__ wsh, const float* __restrict__ bsh,
    const float* __restrict__ wfin, const float* __restrict__ Wq,
    const float* __restrict__ Wv, const float* __restrict__ Wq2,
    const float* __restrict__ Wk, const float* __restrict__ Wk2,
    const float* __restrict__ sla, const float* __restrict__ sle,
    float* __restrict__ pred)
{
    __shared__ float sh[5200];
    const int t = threadIdx.x;
    const unsigned NB = gridDim.x;

    // S0
    for (unsigned tt = blockIdx.x; tt < 7302u; tt += NB){
        if (tt < 1280u){
            int cx = tt & 15, cy = (tt >> 4) & 15, z = tt >> 8;
            tile_transpose(Wk + (long)z*HH, g_WkT + (long)z*HH, Hn, Hn, cx*32, cy*32, sh, t);
        } else if (tt < 2560u){
            unsigned u = tt - 1280u;
            int cx = u & 15, cy = (u >> 4) & 15, z = u >> 8;
            tile_transpose(Wk2 + (long)z*HH, g_Wk2T + (long)z*HH, Hn, Hn, cx*32, cy*32, sh, t);
        } else if (tt < 6656u){
            unsigned u = tt - 2560u;
            int cx = u & 15, cy = (u >> 4) & 3, z = u >> 6;
            tile_transpose(sent + (long)z*Nn*Hn, g_sentT + (long)z*Hn*Nn, Nn, Hn, cx*32, cy*32, sh, t);
        } else if (tt < 7296u){
            tile_wal(sent, aidx, (int)(tt - 6656u), t);
        } else if (tt < 7301u){
            tile_us(Wt, btr, wsh, bsh, wfin, (int)(tt - 7296u), t);
        } else {
            tile_maskdetect((const unsigned char*)mask, sh, t);
        }
    }
    grid_barrier();

    // S1: predg (75 tiles of 256 rows) + Q1 (200)
    {
        OpQ1 op{Wq, sla};
        for (unsigned tt = blockIdx.x; tt < 275u; tt += NB){
            if (tt < 75u) tile_predg(ctx, pred, (int)tt*256, sh, t);
            else {
                unsigned q = tt - 75u;
                tile_gemm128(op, (int)(q % 10u)*64, (int)((q/10u) % 4u)*128, (int)(q/40u), sh, t);
            }
        }
    }
    grid_barrier();

    // S2: margin (640) + T (1600)
    {
        OpT op{};
        for (unsigned tt = blockIdx.x; tt < 2240u; tt += NB){
            if (tt < 640u) tile_margin(pred, mask, (int)tt, t);
            else {
                unsigned q = tt - 640u;
                tile_gemm128(op, (int)(q % 10u)*64, (int)((q/10u) % 4u)*128, (int)(q/40u), sh, t);
            }
        }
    }
    grid_barrier();

    // S3: SC1 (448)
    {
        OpSC1 op{};
        for (unsigned tt = blockIdx.x; tt < 448u; tt += NB)
            tile_gemm128(op, (int)(tt % 7u)*64, 0, (int)(tt/7u), sh, t);
    }
    grid_barrier();

    // S4: sm1
    for (unsigned tt = blockIdx.x; tt < 1600u; tt += NB) tile_sm1((int)tt, t);
    grid_barrier();

    // S5: U
    {
        OpU op{sent};
        for (unsigned tt = blockIdx.x; tt < 1792u; tt += NB)
            tile_gemm128(op, (int)(tt % 7u)*64, (int)((tt/7u) % 4u)*128, (int)(tt/28u), sh, t);
    }
    grid_barrier();

    // S6: CTX1
    {
        OpCTX1 op{Wv};
        for (unsigned tt = blockIdx.x; tt < 400u; tt += NB)
            tile_gemm64(op, (int)(tt % 10u)*64, 0, (int)(tt/10u), sh, t);
    }
    grid_barrier();

    // S7: Q2
    {
        OpQ2 op{Wq2, sle};
        for (unsigned tt = blockIdx.x; tt < 200u; tt += NB)
            tile_gemm128(op, (int)(tt % 10u)*64, (int)((tt/10u) % 4u)*128, (int)(tt/40u), sh, t);
    }
    grid_barrier();

    // S8: R
    {
        OpR op{};
        for (unsigned tt = blockIdx.x; tt < 1600u; tt += NB)
            tile_gemm128(op, (int)(tt % 10u)*64, (int)((tt/10u) % 4u)*128, (int)(tt/40u), sh, t);
    }
}

// ---------------- stage2 ----------------
#define CP 520
__global__ void k_stage2(const float* __restrict__ ctx, const void* __restrict__ mask,
                         const float* __restrict__ Wind, const float* __restrict__ bind,
                         float* __restrict__ ind_out){
    extern __shared__ float smem[];
    float* ctx_sh   = smem;
    float* r_sh     = ctx_sh + Kn*CP;
    float* alias_sh = r_sh + NHn*CP;
    float* ew_sh    = alias_sh + Hn;
    float* red      = ew_sh + NHn*32;

    int blk = blockIdx.x;
    int m = blk % Mn; int bs = blk / Mn; int s = bs % Sn; int b = bs / Sn;
    int bm = b*Mn + m;
    int tid = threadIdx.x;
    for (int i = tid; i < Kn*Hn; i += 256){
        int r = i >> 9, h = i & 511;
        ctx_sh[r*CP + h] = ctx[((long)bm*Kn + r)*Hn + h];
    }
    for (int i = tid; i < NHn*Hn; i += 256){
        int a = i >> 9, h = i & 511;
        r_sh[a*CP + h] = g_r[((long)blk*NHn + a)*Hn + h];
    }
    __syncthreads();

    int a = tid >> 5, k = tid & 31;
    {
        bool act = (k < Kn);
        float acc = 0.f;
        if (act){
            const float4* cp = reinterpret_cast<const float4*>(ctx_sh + k*CP);
            const float4* rp = reinterpret_cast<const float4*>(r_sh + a*CP);
            for (int h4 = 0; h4 < Hn/4; h4++){
                float4 c = cp[h4], rr = rp[h4];
                acc += c.x*rr.x + c.y*rr.y + c.z*rr.z + c.w*rr.w;
            }
        }
        float x = NEG_BIG;
        if (act) x = mask_padded(mask, bm*Kn + k) ? NEG_BIG : acc*0.125f;
        float mx = wmaxf(act ? x : NEG_INF);
        float e = act ? expf(x - mx) : 0.f;
        float sv = wsum(e);
        if (act) ew_sh[a*32 + k] = e/sv;
    }
    __syncthreads();
    for (int g = tid; g < Hn; g += 256){
        int ah = g >> 6;
        float acc = 0.f;
#pragma unroll
        for (int kk = 0; kk < Kn; kk++) acc += ew_sh[ah*32 + kk]*ctx_sh[kk*CP + g];
        alias_sh[g] = acc;
    }
    __syncthreads();
    float p0 = 0.f, p1 = 0.f;
    for (int g = tid; g < Hn; g += 256){
        float av = alias_sh[g];
        p0 += av*Wind[(s*Hn + g)*2 + 0];
        p1 += av*Wind[(s*Hn + g)*2 + 1];
    }
    p0 = wsum(p0); p1 = wsum(p1);
    if ((tid & 31) == 0){ red[(tid >> 5)*2] = p0; red[(tid >> 5)*2 + 1] = p1; }
    __syncthreads();
    if (tid == 0){
        float i0 = 0.f, i1 = 0.f;
        for (int wv = 0; wv < 8; wv++){ i0 += red[wv*2]; i1 += red[wv*2 + 1]; }
        i0 += bind[s*2 + 0]; i1 += bind[s*2 + 1];
        ind_out[blk*2 + 0] = i0;
        ind_out[blk*2 + 1] = i1;
        float mx = fmaxf(i0, i1);
        float lse = mx + logf(expf(i0 - mx) + expf(i1 - mx));
        g_indp[bm*Sn + s] = i1 - lse;
    }
}

__global__ void k_attn_beff(const float* __restrict__ btr){
    __shared__ float at[Sn];
    int bm = blockIdx.x, t = threadIdx.x;
    if (t < 32){
        int s = t;
        bool act = (s < Sn);
        float x = act ? (g_indp[bm*Sn + s] + g_margin[bm*Sn + s])*4.0f : NEG_INF;
        float mx = wmaxf(x);
        float e = act ? expf(x - mx) : 0.f;
        float sm = wsum(e);
        if (act){ float v = e/sm; g_attn[bm*Sn + s] = v; at[s] = v; }
    }
    __syncthreads();
    float acc = 0.f;
#pragma unroll
    for (int s = 0; s < Sn; s++) acc += at[s]*btr[s*Hn + t];
    g_beff[bm*Hn + t] = acc;
}

__global__ void k_finalv(const float* __restrict__ bfin, float* __restrict__ out){
    int i = blockIdx.x*256 + threadIdx.x;
    if (i >= BMKn) return;
    int bm = i / Kn;
    float acc = bfin[0];
#pragma unroll
    for (int s = 0; s < Sn; s++) acc += g_attn[bm*Sn + s]*g_fdot[i*Sn + s];
    out[i] = acc;
}

// ---------------- REW (R11 measured-best): weff + rew2, fp32 ----------------
__global__ __launch_bounds__(256) void k_weff(const float* __restrict__ Wt){
    __shared__ float at[BMn*Sn];
    const int k0 = blockIdx.x*32, n0 = blockIdx.y*64;
    const int t = threadIdx.x;
    for (int i = t; i < BMn*Sn; i += 256) at[i] = g_attn[i];
    const int kk = t >> 3, cg = t & 7;
    float w[Sn][8];
#pragma unroll
    for (int s = 0; s < Sn; s++){
        *(float4*)&w[s][0] = *(const float4*)&Wt[((long)s*Hn + k0 + kk)*Hn + n0 + cg*8];
        *(float4*)&w[s][4] = *(const float4*)&Wt[((long)s*Hn + k0 + kk)*Hn + n0 + cg*8 + 4];
    }
    __syncthreads();
    float* dst0 = g_weff + (long)(k0 + kk)*Hn + n0 + cg*8;
    for (int bm = 0; bm < BMn; bm++){
        float a0 = at[bm*Sn+0], a1 = at[bm*Sn+1], a2 = at[bm*Sn+2],
              a3 = at[bm*Sn+3], a4 = at[bm*Sn+4];
        float o[8];
#pragma unroll
        for (int j = 0; j < 8; j++)
            o[j] = a0*w[0][j] + a1*w[1][j] + a2*w[2][j] + a3*w[3][j] + a4*w[4][j];
        float* dst = dst0 + (long)bm*HH;
        *(float4*)dst       = *(float4*)&o[0];
        *(float4*)(dst + 4) = *(float4*)&o[4];
    }
}

__global__ __launch_bounds__(256) void k_rew2(const float* __restrict__ ctx,
                                              float* __restrict__ outp){
    __shared__ float As[16][33];
    __shared__ float Bs[16][256];
    const int bm   = blockIdx.x >> 1;
    const int col0 = (blockIdx.x & 1) << 8;
    const int t  = threadIdx.x;
    const int tc = t & 63;
    const int tr = t >> 6;
    float acc[8][4];
#pragma unroll
    for (int i = 0; i < 8; i++)
#pragma unroll
        for (int j = 0; j < 4; j++) acc[i][j] = 0.f;

    const float* cpb = ctx + (long)bm*Kn*Hn;
    const float* Wf  = g_weff + (long)bm*HH;

    for (int k0 = 0; k0 < Hn; k0 += 16){
#pragma unroll
        for (int i = t; i < 512; i += 256){
            int r = i >> 4, kk = i & 15;
            As[kk][r] = (r < Kn) ? cpb[r*Hn + k0 + kk] : 0.f;
        }
#pragma unroll
        for (int p = 0; p < 4; p++){
            int kk = (t >> 6) + p*4;
            int cc = (t & 63)*4;
            *(float4*)&Bs[kk][cc] = *(const float4*)&Wf[(long)(k0 + kk)*Hn + col0 + cc];
        }
        __syncthreads();
#pragma unroll
        for (int kk = 0; kk < 16; kk++){
            float4 b = *(float4*)&Bs[kk][tc*4];
            float a[8];
#pragma unroll
            for (int i = 0; i < 8; i++) a[i] = As[kk][tr*8 + i];
#pragma unroll
            for (int i = 0; i < 8; i++){
                acc[i][0] += a[i]*b.x;
                acc[i][1] += a[i]*b.y;
                acc[i][2] += a[i]*b.z;
                acc[i][3] += a[i]*b.w;
            }
        }
        __syncthreads();
    }
    float4 be = *(const float4*)&g_beff[bm*Hn + col0 + tc*4];
#pragma unroll
    for (int i = 0; i < 8; i++){
        int r = tr*8 + i;
        if (r < Kn){
            float4 v;
            v.x = acc[i][0] + be.x;
            v.y = acc[i][1] + be.y;
            v.z = acc[i][2] + be.z;
            v.w = acc[i][3] + be.w;
            *(float4*)&outp[((long)(bm*Kn + r))*Hn + col0 + tc*4] = v;
        }
    }
}

// ---------------- host launcher ----------------
extern "C" void kernel_launch(void* const* d_in, const int* in_sizes, int n_in,
                              void* d_out, int out_size){
    const float* ctx  = (const float*)d_in[0];
    const float* sent = (const float*)d_in[1];
    const int*   aidx = (const int*)d_in[2];
    const void*  mask = (const void*)d_in[3];
    const float* Wtr  = (const float*)d_in[4];
    const float* btr  = (const float*)d_in[5];
    const float* Wind = (const float*)d_in[6];
    const float* bind = (const float*)d_in[7];
    const float* Wq   = (const float*)d_in[8];
    const float* Wk   = (const float*)d_in[9];
    const float* Wv   = (const float*)d_in[10];
    const float* Wq2  = (const float*)d_in[11];
    const float* Wk2  = (const float*)d_in[12];
    const float* sla  = (const float*)d_in[13];
    const float* sle  = (const float*)d_in[14];
    const float* wsh  = (const float*)d_in[15];
    const float* bsh  = (const float*)d_in[16];
    const float* wfin = (const float*)d_in[17];
    const float* bfin = (const float*)d_in[18];
    float* out = (float*)d_out;

    void* tmp;
    cudaGetSymbolAddress(&tmp, g_pred_s); float* pred_s = (float*)tmp;
    cudaGetSymbolAddress(&tmp, g_ind_s);  float* ind_s  = (float*)tmp;

    const bool big_out = (out_size >= (BMKn + BMKn*Hn + BMKn*Sn + Bn*Sn*Mn*2));
    float *p_final = out;
    float *p_rew  = big_out ? out + BMKn : nullptr;
    float *p_pred = big_out ? out + BMKn + BMKn*Hn : pred_s;
    float *p_ind  = big_out ? out + BMKn + BMKn*Hn + BMKn*Sn : ind_s;

    cudaFuncSetAttribute(k_stage2, cudaFuncAttributeMaxDynamicSharedMemorySize, 90*1024);

    int dev = 0; cudaGetDevice(&dev);
    int sms = 148;
    cudaDeviceGetAttribute(&sms, cudaDevAttrMultiProcessorCount, dev);
    int nb = 0;
    cudaOccupancyMaxActiveBlocksPerMultiprocessor(&nb, k_mega, 256, 0);
    if (nb < 4) nb = 4;
    int grid = nb * sms;

    k_mega<<<grid, 256>>>(sent, aidx, mask, ctx, Wtr, btr, wsh, bsh, wfin,
                          Wq, Wv, Wq2, Wk, Wk2, sla, sle, p_pred);

    size_t sm2 = (size_t)(Kn*CP + NHn*CP + Hn + NHn*32 + 16)*sizeof(float);
    k_stage2<<<Bn*Sn*Mn, 256, sm2>>>(ctx, mask, Wind, bind, p_ind);

    k_attn_beff<<<BMn, 512>>>(btr);

    if (big_out){
        k_weff<<<dim3(16, 8), 256>>>(Wtr);
        k_rew2<<<BMn*2, 256>>>(ctx, p_rew);
    }
    k_finalv<<<(BMKn + 255)/256, 256>>>(bfin, p_final);
}

// round 15
// speedup vs baseline: 1.0429x; 1.0234x over previous
#include <cuda_runtime.h>
#include <math.h>

#define Bn   64
#define Mn   10
#define Kn   30
#define Hn   512
#define Nn   128
#define Sn   5
#define NHn  8
#define DHn  64
#define BMn  640
#define BMKn 19200
#define HH   (Hn*Hn)

#define NEG_BIG (-1.0e9f)
#define NEG_INF (-3.402823e38f)

// ---------------- scratch ----------------
__device__ float g_wal  [BMn*Hn];
__device__ float g_sentT[Bn*Hn*Nn];
__device__ float g_WkT  [Sn*HH];
__device__ float g_Wk2T [Sn*HH];
__device__ float g_q1   [Bn*Sn*Mn*Hn];
__device__ float g_t    [Bn*Sn*Mn*NHn*Hn];
__device__ float g_sc1  [Bn*Sn*Mn*NHn*Nn];
__device__ float g_u    [Bn*Sn*Mn*NHn*Hn];
__device__ float g_ctx1 [Bn*Sn*Mn*Hn];
__device__ float g_q2   [Bn*Sn*Mn*Hn];
__device__ float g_r    [Bn*Sn*Mn*NHn*Hn];
__device__ float g_us   [Sn*Hn];
__device__ float g_vs   [Sn*Hn];
__device__ float g_ds   [Sn];
__device__ float g_es   [Sn];
__device__ float g_indp [BMn*Sn];
__device__ float g_margin[BMn*Sn];
__device__ float g_attn [BMn*Sn];
__device__ float g_beff [BMn*Hn];
__device__ float g_fdot [BMKn*Sn];
__device__ int   g_mask_mode;
// weff in tile-blocked layout: [tile(kt*8+nt)][bm][kk(32)*64 + c]
__device__ float g_weff [BMn*(long)HH];
__device__ float g_pred_s[BMKn*Sn];
__device__ float g_ind_s [Bn*Sn*Mn*2];
__device__ unsigned g_bar_count = 0;
__device__ unsigned g_bar_gen   = 0;

// ---------------- warp helpers ----------------
__device__ __forceinline__ float wsum(float v){
#pragma unroll
    for (int o = 16; o; o >>= 1) v += __shfl_xor_sync(0xffffffffu, v, o);
    return v;
}
__device__ __forceinline__ float wmaxf(float v){
#pragma unroll
    for (int o = 16; o; o >>= 1) v = fmaxf(v, __shfl_xor_sync(0xffffffffu, v, o));
    return v;
}

__device__ __forceinline__ bool mask_padded(const void* m, int idx){
    int mode = g_mask_mode;
    if (mode == 0) return ((const unsigned char*)m)[idx] != 0;
    if (mode == 1) return ((const int*)m)[idx] != 0;
    return ((const float*)m)[idx] != 0.f;
}

// ---------------- software grid barrier ----------------
__device__ __forceinline__ void grid_barrier(){
    __syncthreads();
    if (threadIdx.x == 0){
        __threadfence();
        unsigned gen = atomicAdd(&g_bar_gen, 0u);
        unsigned t = atomicAdd(&g_bar_count, 1u);
        if (t == gridDim.x - 1u){
            atomicExch(&g_bar_count, 0u);
            __threadfence();
            atomicAdd(&g_bar_gen, 1u);
        } else {
            while (atomicAdd(&g_bar_gen, 0u) == gen) __nanosleep(64);
        }
        __threadfence();
    }
    __syncthreads();
}

// ---------------- op functors ----------------
struct OpQ1 {
    const float* Wq; const float* slice;
    static constexpr int ROWS = BMn, KD = Hn;
    __device__ float loadA(int z, int row, int k) const {
        return g_wal[row*Hn + k] + slice[z*Hn + k];
    }
    __device__ float loadB(int z, int k, int n) const { return Wq[(long)z*HH + k*Hn + n]; }
    __device__ void store(int z, int row, int col, float v) const {
        int b = row/Mn, m = row - b*Mn;
        g_q1[((b*Sn + z)*Mn + m)*Hn + col] = v;
    }
};
struct OpT {
    static constexpr int ROWS = BMn, KD = DHn;
    __device__ float loadA(int z, int row, int k) const {
        int s = z >> 3, a = z & 7; int b = row/Mn, m = row - b*Mn;
        return g_q1[((b*Sn + s)*Mn + m)*Hn + a*DHn + k];
    }
    __device__ float loadB(int z, int k, int n) const {
        int s = z >> 3, a = z & 7;
        return g_WkT[(long)s*HH + (a*DHn + k)*Hn + n];
    }
    __device__ void store(int z, int row, int col, float v) const {
        int s = z >> 3, a = z & 7; int b = row/Mn, m = row - b*Mn;
        g_t[(((b*Sn + s)*Mn + m)*NHn + a)*Hn + col] = v;
    }
};
struct OpR {
    static constexpr int ROWS = BMn, KD = DHn;
    __device__ float loadA(int z, int row, int k) const {
        int s = z >> 3, a = z & 7; int b = row/Mn, m = row - b*Mn;
        return g_q2[((b*Sn + s)*Mn + m)*Hn + a*DHn + k];
    }
    __device__ float loadB(int z, int k, int n) const {
        int s = z >> 3, a = z & 7;
        return g_Wk2T[(long)s*HH + (a*DHn + k)*Hn + n];
    }
    __device__ void store(int z, int row, int col, float v) const {
        int s = z >> 3, a = z & 7; int b = row/Mn, m = row - b*Mn;
        g_r[(((b*Sn + s)*Mn + m)*NHn + a)*Hn + col] = v;
    }
};
struct OpSC1 {
    static constexpr int ROWS = 400, KD = Hn;
    __device__ float loadA(int z, int row, int k) const { return g_t[((long)z*400 + row)*Hn + k]; }
    __device__ float loadB(int z, int k, int n) const { return g_sentT[((long)z*Hn + k)*Nn + n]; }
    __device__ void store(int z, int row, int col, float v) const {
        g_sc1[((long)z*400 + row)*Nn + col] = 0.125f * v;
    }
};
struct OpU {
    const float* sent;
    static constexpr int ROWS = 400, KD = Nn;
    __device__ float loadA(int z, int row, int k) const { return g_sc1[((long)z*400 + row)*Nn + k]; }
    __device__ float loadB(int z, int k, int n) const { return sent[((long)z*Nn + k)*Hn + n]; }
    __device__ void store(int z, int row, int col, float v) const {
        g_u[((long)z*400 + row)*Hn + col] = v;
    }
};
struct OpCTX1 {
    const float* Wv;
    static constexpr int ROWS = BMn, KD = Hn;
    __device__ float loadA(int z, int row, int k) const {
        int s = z >> 3, a = z & 7; int b = row/Mn, m = row - b*Mn;
        return g_u[(((b*Sn + s)*Mn + m)*NHn + a)*Hn + k];
    }
    __device__ float loadB(int z, int k, int n) const {
        int s = z >> 3, a = z & 7;
        return Wv[(long)s*HH + k*Hn + a*DHn + n];
    }
    __device__ void store(int z, int row, int col, float v) const {
        int s = z >> 3, a = z & 7; int b = row/Mn, m = row - b*Mn;
        g_ctx1[((b*Sn + s)*Mn + m)*Hn + a*DHn + col] = v;
    }
};
struct OpQ2 {
    const float* Wq2; const float* slice;
    static constexpr int ROWS = BMn, KD = Hn;
    __device__ float loadA(int z, int row, int k) const {
        int b = row/Mn, m = row - b*Mn;
        return g_ctx1[((b*Sn + z)*Mn + m)*Hn + k] + slice[z*Hn + k];
    }
    __device__ float loadB(int z, int k, int n) const { return Wq2[(long)z*HH + k*Hn + n]; }
    __device__ void store(int z, int row, int col, float v) const {
        int b = row/Mn, m = row - b*Mn;
        g_q2[((b*Sn + z)*Mn + m)*Hn + col] = v;
    }
};

// ---------------- tile device functions ----------------
template <class OP>
__device__ void tile_gemm128(const OP& op, int row0, int col0, int z, float* sh, int t){
    float* As = sh;
    float* Bs = sh + 1040;
    const int tr = t >> 5, tc = t & 31;
    float acc[8][4];
#pragma unroll
    for (int i = 0; i < 8; i++)
#pragma unroll
        for (int j = 0; j < 4; j++) acc[i][j] = 0.f;

    for (int k0 = 0; k0 < OP::KD; k0 += 16){
#pragma unroll
        for (int i = 0; i < 4; i++){
            int idx = t + i*256;
            int rr = idx >> 4, kk = idx & 15;
            int row = row0 + rr;
            As[kk*65 + rr] = (row < OP::ROWS) ? op.loadA(z, row, k0 + kk) : 0.f;
        }
#pragma unroll
        for (int i = 0; i < 8; i++){
            int idx = t + i*256;
            int kk = idx >> 7, nn = idx & 127;
            Bs[kk*128 + nn] = op.loadB(z, k0 + kk, col0 + nn);
        }
        __syncthreads();
#pragma unroll
        for (int kk = 0; kk < 16; kk++){
            float4 b = *(const float4*)&Bs[kk*128 + tc*4];
            float a[8];
#pragma unroll
            for (int i = 0; i < 8; i++) a[i] = As[kk*65 + tr*8 + i];
#pragma unroll
            for (int i = 0; i < 8; i++){
                acc[i][0] += a[i]*b.x;
                acc[i][1] += a[i]*b.y;
                acc[i][2] += a[i]*b.z;
                acc[i][3] += a[i]*b.w;
            }
        }
        __syncthreads();
    }
#pragma unroll
    for (int i = 0; i < 8; i++){
        int row = row0 + tr*8 + i;
        if (row >= OP::ROWS) continue;
#pragma unroll
        for (int j = 0; j < 4; j++) op.store(z, row, col0 + tc*4 + j, acc[i][j]);
    }
    __syncthreads();
}

template <class OP>
__device__ void tile_gemm64(const OP& op, int row0, int col0, int z, float* sh, int t){
    float* As = sh;
    float* Bs = sh + 1040;
    const int tr = t >> 5, tc = t & 31;
    float acc[8][2];
#pragma unroll
    for (int i = 0; i < 8; i++){ acc[i][0] = 0.f; acc[i][1] = 0.f; }

    for (int k0 = 0; k0 < OP::KD; k0 += 16){
#pragma unroll
        for (int i = 0; i < 4; i++){
            int idx = t + i*256;
            int rr = idx >> 4, kk = idx & 15;
            int row = row0 + rr;
            As[kk*65 + rr] = (row < OP::ROWS) ? op.loadA(z, row, k0 + kk) : 0.f;
        }
#pragma unroll
        for (int i = 0; i < 4; i++){
            int idx = t + i*256;
            int kk = idx >> 6, nn = idx & 63;
            Bs[kk*64 + nn] = op.loadB(z, k0 + kk, col0 + nn);
        }
        __syncthreads();
#pragma unroll
        for (int kk = 0; kk < 16; kk++){
            float2 b = *(const float2*)&Bs[kk*64 + tc*2];
            float a[8];
#pragma unroll
            for (int i = 0; i < 8; i++) a[i] = As[kk*65 + tr*8 + i];
#pragma unroll
            for (int i = 0; i < 8; i++){
                acc[i][0] += a[i]*b.x;
                acc[i][1] += a[i]*b.y;
            }
        }
        __syncthreads();
    }
#pragma unroll
    for (int i = 0; i < 8; i++){
        int row = row0 + tr*8 + i;
        if (row >= OP::ROWS) continue;
        op.store(z, row, col0 + tc*2, acc[i][0]);
        op.store(z, row, col0 + tc*2 + 1, acc[i][1]);
    }
    __syncthreads();
}

__device__ void tile_transpose(const float* in, float* out, int R, int C,
                               int c0, int r0, float* sh, int t){
    float* tile = sh;
    int tx = t & 31, ty = t >> 5;
#pragma unroll
    for (int i = 0; i < 32; i += 8){
        int r = r0 + ty + i, c = c0 + tx;
        tile[(ty + i)*33 + tx] = (r < R && c < C) ? in[(long)r*C + c] : 0.f;
    }
    __syncthreads();
#pragma unroll
    for (int i = 0; i < 32; i += 8){
        int c = c0 + ty + i, r = r0 + tx;
        if (c < C && r < R) out[(long)c*R + r] = tile[tx*33 + ty + i];
    }
    __syncthreads();
}

__device__ void tile_wal(const float* sent, const int* aidx, int bm, int t){
    int b = bm / Mn;
    int idx = aidx[bm];
    const float* src = sent + ((long)b*Nn + idx)*Hn;
#pragma unroll
    for (int i = 0; i < 2; i++) g_wal[bm*Hn + t + i*256] = src[t + i*256];
}

__device__ void tile_us(const float* Wt, const float* btr, const float* wsh,
                        const float* bsh, const float* wfin, int s, int t){
    int w = t >> 5, lane = t & 31;
    for (int h = w; h < Hn; h += 8){
        const float* wrow = Wt + ((long)s*Hn + h)*Hn;
        float aU = 0.f, aV = 0.f;
        for (int g = lane; g < Hn; g += 32){
            float x = wrow[g];
            aU += x*wsh[g];
            aV += x*wfin[g];
        }
        aU = wsum(aU); aV = wsum(aV);
        if (lane == 0){ g_us[s*Hn + h] = aU; g_vs[s*Hn + h] = aV; }
    }
    if (w == 0){
        float dU = 0.f, dV = 0.f;
        for (int h = lane; h < Hn; h += 32){
            float b = btr[s*Hn + h];
            dU += b*wsh[h];
            dV += b*wfin[h];
        }
        dU = wsum(dU); dV = wsum(dV);
        if (lane == 0){ g_ds[s] = dU + bsh[0]; g_es[s] = dV; }
    }
}

__device__ void tile_maskdetect(const unsigned char* m, float* sh, int t){
    int* si = (int*)sh;
    if (t == 0){ si[0] = 0; si[1] = 0; }
    __syncthreads();
    int c1 = 0, c2 = 0;
    for (int i = t; i < BMKn; i += 256){
        unsigned char v = m[i];
        if (v > 1) c2++;
        else if (v == 1 && (i & 3)) c1++;
    }
    atomicAdd(&si[0], c1);
    atomicAdd(&si[1], c2);
    __syncthreads();
    if (t == 0) g_mask_mode = (si[1] > 0) ? 2 : ((si[0] > 0) ? 0 : 1);
    __syncthreads();
}

// batched pred: 256 bmk rows per tile; basis [us|vs] staged in smem
__device__ void tile_predg(const float* ctx, float* pred, int row0, float* sh, int t){
    for (int i = t; i < 5120; i += 256)
        sh[i] = (i < 2560) ? g_us[i] : g_vs[i - 2560];
    __syncthreads();
    int w = t >> 5, lane = t & 31;
    int rbase = row0 + w*32;
#pragma unroll 1
    for (int i = 0; i < 32; i++){
        int r = rbase + i;
        const float* cp = ctx + (long)r*Hn;
        float a[16];
#pragma unroll
        for (int j = 0; j < 16; j++) a[j] = cp[lane + 32*j];
#pragma unroll
        for (int d = 0; d < 10; d++){
            const float* vv = sh + d*512;
            float acc = 0.f;
#pragma unroll
            for (int j = 0; j < 16; j++) acc += a[j]*vv[lane + 32*j];
            acc = wsum(acc);
            if (lane == 0){
                if (d < Sn) pred[r*Sn + d] = acc + g_ds[d];
                else        g_fdot[r*Sn + (d - Sn)] = acc + g_es[d - Sn];
            }
        }
    }
    __syncthreads();
}

__device__ void tile_margin(const float* pred, const void* mask, int bm, int t){
    int w = t >> 5, k = t & 31;
    if (w >= Sn) return;
    bool act = (k < Kn);
    float logit = NEG_BIG;
    if (act){
        float pv = pred[(bm*Kn + k)*Sn + w];
        logit = mask_padded(mask, bm*Kn + k) ? NEG_BIG : pv;
    }
    float mx = wmaxf(act ? logit : NEG_INF);
    float e = act ? expf(logit - mx) : 0.f;
    float sm = wsum(e);
    float lse = logf(sm);
    float conf = act ? (logit - mx - lse) : NEG_INF;
    float v = conf; int idx = k;
#pragma unroll
    for (int o = 16; o; o >>= 1){
        float v2 = __shfl_xor_sync(0xffffffffu, v, o);
        int   i2 = __shfl_xor_sync(0xffffffffu, idx, o);
        if (v2 > v || (v2 == v && i2 < idx)){ v = v2; idx = i2; }
    }
    float c2 = (act && k != idx) ? conf : NEG_INF;
    float v2m = wmaxf(c2);
    if (k == 0) g_margin[bm*Sn + w] = (v - v2m) / (v + v2m);
}

__device__ void tile_sm1(int grp, int t){
    int w = t >> 5, lane = t & 31;
#pragma unroll
    for (int rr = 0; rr < 2; rr++){
        long row = (long)grp*16 + w + rr*8;
        float v[4]; float mx = NEG_INF;
#pragma unroll
        for (int i = 0; i < 4; i++){ v[i] = g_sc1[row*Nn + lane + 32*i]; mx = fmaxf(mx, v[i]); }
        mx = wmaxf(mx);
        float sm = 0.f;
#pragma unroll
        for (int i = 0; i < 4; i++){ v[i] = expf(v[i] - mx); sm += v[i]; }
        sm = wsum(sm);
        float inv = 1.f/sm;
#pragma unroll
        for (int i = 0; i < 4; i++) g_sc1[row*Nn + lane + 32*i] = v[i]*inv;
    }
}

// ---------------- persistent megakernel ----------------
__global__ __launch_bounds__(256, 4) void k_mega(
    const float* __restrict__ sent, const int* __restrict__ aidx,
    const void* __restrict__ mask, const float* __restrict__ ctx,
    const float* __restrict__ Wt, const float* __restrict__ btr,
    const float* __restrict__ wsh, const float* __restrict__ bsh,
    const float* __restrict__ wfin, const float* __restrict__ Wq,
    const float* __restrict__ Wv, const float* __restrict__ Wq2,
    const float* __restrict__ Wk, const float* __restrict__ Wk2,
    const float* __restrict__ sla, const float* __restrict__ sle,
    float* __restrict__ pred)
{
    __shared__ float sh[5200];
    const int t = threadIdx.x;
    const unsigned NB = gridDim.x;

    // S0
    for (unsigned tt = blockIdx.x; tt < 7302u; tt += NB){
        if (tt < 1280u){
            int cx = tt & 15, cy = (tt >> 4) & 15, z = tt >> 8;
            tile_transpose(Wk + (long)z*HH, g_WkT + (long)z*HH, Hn, Hn, cx*32, cy*32, sh, t);
        } else if (tt < 2560u){
            unsigned u = tt - 1280u;
            int cx = u & 15, cy = (u >> 4) & 15, z = u >> 8;
            tile_transpose(Wk2 + (long)z*HH, g_Wk2T + (long)z*HH, Hn, Hn, cx*32, cy*32, sh, t);
        } else if (tt < 6656u){
            unsigned u = tt - 2560u;
            int cx = u & 15, cy = (u >> 4) & 3, z = u >> 6;
            tile_transpose(sent + (long)z*Nn*Hn, g_sentT + (long)z*Hn*Nn, Nn, Hn, cx*32, cy*32, sh, t);
        } else if (tt < 7296u){
            tile_wal(sent, aidx, (int)(tt - 6656u), t);
        } else if (tt < 7301u){
            tile_us(Wt, btr, wsh, bsh, wfin, (int)(tt - 7296u), t);
        } else {
            tile_maskdetect((const unsigned char*)mask, sh, t);
        }
    }
    grid_barrier();

    // S1: predg (75) + Q1 (200)
    {
        OpQ1 op{Wq, sla};
        for (unsigned tt = blockIdx.x; tt < 275u; tt += NB){
            if (tt < 75u) tile_predg(ctx, pred, (int)tt*256, sh, t);
            else {
                unsigned q = tt - 75u;
                tile_gemm128(op, (int)(q % 10u)*64, (int)((q/10u) % 4u)*128, (int)(q/40u), sh, t);
            }
        }
    }
    grid_barrier();

    // S2: margin (640) + T (1600)
    {
        OpT op{};
        for (unsigned tt = blockIdx.x; tt < 2240u; tt += NB){
            if (tt < 640u) tile_margin(pred, mask, (int)tt, t);
            else {
                unsigned q = tt - 640u;
                tile_gemm128(op, (int)(q % 10u)*64, (int)((q/10u) % 4u)*128, (int)(q/40u), sh, t);
            }
        }
    }
    grid_barrier();

    // S3: SC1 (448)
    {
        OpSC1 op{};
        for (unsigned tt = blockIdx.x; tt < 448u; tt += NB)
            tile_gemm128(op, (int)(tt % 7u)*64, 0, (int)(tt/7u), sh, t);
    }
    grid_barrier();

    // S4: sm1
    for (unsigned tt = blockIdx.x; tt < 1600u; tt += NB) tile_sm1((int)tt, t);
    grid_barrier();

    // S5: U
    {
        OpU op{sent};
        for (unsigned tt = blockIdx.x; tt < 1792u; tt += NB)
            tile_gemm128(op, (int)(tt % 7u)*64, (int)((tt/7u) % 4u)*128, (int)(tt/28u), sh, t);
    }
    grid_barrier();

    // S6: CTX1
    {
        OpCTX1 op{Wv};
        for (unsigned tt = blockIdx.x; tt < 400u; tt += NB)
            tile_gemm64(op, (int)(tt % 10u)*64, 0, (int)(tt/10u), sh, t);
    }
    grid_barrier();

    // S7: Q2
    {
        OpQ2 op{Wq2, sle};
        for (unsigned tt = blockIdx.x; tt < 200u; tt += NB)
            tile_gemm128(op, (int)(tt % 10u)*64, (int)((tt/10u) % 4u)*128, (int)(tt/40u), sh, t);
    }
    grid_barrier();

    // S8: R
    {
        OpR op{};
        for (unsigned tt = blockIdx.x; tt < 1600u; tt += NB)
            tile_gemm128(op, (int)(tt % 10u)*64, (int)((tt/10u) % 4u)*128, (int)(tt/40u), sh, t);
    }
}

// ---------------- stage2 (CP=524: conflict-free LDS.128 rows) ----------------
#define CP 524
__global__ void k_stage2(const float* __restrict__ ctx, const void* __restrict__ mask,
                         const float* __restrict__ Wind, const float* __restrict__ bind,
                         float* __restrict__ ind_out){
    extern __shared__ float smem[];
    float* ctx_sh   = smem;
    float* r_sh     = ctx_sh + Kn*CP;
    float* alias_sh = r_sh + NHn*CP;
    float* ew_sh    = alias_sh + Hn;
    float* red      = ew_sh + NHn*32;

    int blk = blockIdx.x;
    int m = blk % Mn; int bs = blk / Mn; int s = bs % Sn; int b = bs / Sn;
    int bm = b*Mn + m;
    int tid = threadIdx.x;
    for (int i = tid; i < Kn*Hn; i += 256){
        int r = i >> 9, h = i & 511;
        ctx_sh[r*CP + h] = ctx[((long)bm*Kn + r)*Hn + h];
    }
    for (int i = tid; i < NHn*Hn; i += 256){
        int a = i >> 9, h = i & 511;
        r_sh[a*CP + h] = g_r[((long)blk*NHn + a)*Hn + h];
    }
    __syncthreads();

    int a = tid >> 5, k = tid & 31;
    {
        bool act = (k < Kn);
        float acc = 0.f;
        if (act){
            const float4* cp = reinterpret_cast<const float4*>(ctx_sh + k*CP);
            const float4* rp = reinterpret_cast<const float4*>(r_sh + a*CP);
            for (int h4 = 0; h4 < Hn/4; h4++){
                float4 c = cp[h4], rr = rp[h4];
                acc += c.x*rr.x + c.y*rr.y + c.z*rr.z + c.w*rr.w;
            }
        }
        float x = NEG_BIG;
        if (act) x = mask_padded(mask, bm*Kn + k) ? NEG_BIG : acc*0.125f;
        float mx = wmaxf(act ? x : NEG_INF);
        float e = act ? expf(x - mx) : 0.f;
        float sv = wsum(e);
        if (act) ew_sh[a*32 + k] = e/sv;
    }
    __syncthreads();
    for (int g = tid; g < Hn; g += 256){
        int ah = g >> 6;
        float acc = 0.f;
#pragma unroll
        for (int kk = 0; kk < Kn; kk++) acc += ew_sh[ah*32 + kk]*ctx_sh[kk*CP + g];
        alias_sh[g] = acc;
    }
    __syncthreads();
    float p0 = 0.f, p1 = 0.f;
    for (int g = tid; g < Hn; g += 256){
        float av = alias_sh[g];
        p0 += av*Wind[(s*Hn + g)*2 + 0];
        p1 += av*Wind[(s*Hn + g)*2 + 1];
    }
    p0 = wsum(p0); p1 = wsum(p1);
    if ((tid & 31) == 0){ red[(tid >> 5)*2] = p0; red[(tid >> 5)*2 + 1] = p1; }
    __syncthreads();
    if (tid == 0){
        float i0 = 0.f, i1 = 0.f;
        for (int wv = 0; wv < 8; wv++){ i0 += red[wv*2]; i1 += red[wv*2 + 1]; }
        i0 += bind[s*2 + 0]; i1 += bind[s*2 + 1];
        ind_out[blk*2 + 0] = i0;
        ind_out[blk*2 + 1] = i1;
        float mx = fmaxf(i0, i1);
        float lse = mx + logf(expf(i0 - mx) + expf(i1 - mx));
        g_indp[bm*Sn + s] = i1 - lse;
    }
}

__global__ void k_attn_beff(const float* __restrict__ btr){
    __shared__ float at[Sn];
    int bm = blockIdx.x, t = threadIdx.x;
    if (t < 32){
        int s = t;
        bool act = (s < Sn);
        float x = act ? (g_indp[bm*Sn + s] + g_margin[bm*Sn + s])*4.0f : NEG_INF;
        float mx = wmaxf(x);
        float e = act ? expf(x - mx) : 0.f;
        float sm = wsum(e);
        if (act){ float v = e/sm; g_attn[bm*Sn + s] = v; at[s] = v; }
    }
    __syncthreads();
    float acc = 0.f;
#pragma unroll
    for (int s = 0; s < Sn; s++) acc += at[s]*btr[s*Hn + t];
    g_beff[bm*Hn + t] = acc;
}

__global__ void k_finalv(const float* __restrict__ bfin, float* __restrict__ out){
    int i = blockIdx.x*256 + threadIdx.x;
    if (i >= BMKn) return;
    int bm = i / Kn;
    float acc = bfin[0];
#pragma unroll
    for (int s = 0; s < Sn; s++) acc += g_attn[bm*Sn + s]*g_fdot[i*Sn + s];
    out[i] = acc;
}

// ---------------- REW phase 1: Weff, tile-blocked streaming layout ----------------
// weff tile (kt,nt): g_weff[((kt*8+nt)*BMn + bm)*2048 + kk*64 + c], kk in [0,32), c in [0,64).
// Block (kt,nt) writes 640 ADJACENT 8KB tiles = 5.2MB contiguous stream.
__global__ __launch_bounds__(256) void k_weff(const float* __restrict__ Wt){
    __shared__ float at[BMn*Sn];
    const int kt = blockIdx.x, nt = blockIdx.y;
    const int k0 = kt*32, n0 = nt*64;
    const int t = threadIdx.x;
    for (int i = t; i < BMn*Sn; i += 256) at[i] = g_attn[i];
    const int kk = t >> 3, cg = t & 7;
    float w[Sn][8];
#pragma unroll
    for (int s = 0; s < Sn; s++){
        *(float4*)&w[s][0] = *(const float4*)&Wt[((long)s*Hn + k0 + kk)*Hn + n0 + cg*8];
        *(float4*)&w[s][4] = *(const float4*)&Wt[((long)s*Hn + k0 + kk)*Hn + n0 + cg*8 + 4];
    }
    __syncthreads();
    float* dst0 = g_weff + ((long)(kt*8 + nt)*BMn)*2048 + kk*64 + cg*8;
    for (int bm = 0; bm < BMn; bm++){
        float a0 = at[bm*Sn+0], a1 = at[bm*Sn+1], a2 = at[bm*Sn+2],
              a3 = at[bm*Sn+3], a4 = at[bm*Sn+4];
        float o[8];
#pragma unroll
        for (int j = 0; j < 8; j++)
            o[j] = a0*w[0][j] + a1*w[1][j] + a2*w[2][j] + a3*w[3][j] + a4*w[4][j];
        float* dst = dst0 + (long)bm*2048;
        *(float4*)dst       = *(float4*)&o[0];
        *(float4*)(dst + 4) = *(float4*)&o[4];
    }
}

// ---------------- REW phase 2: reads tile-blocked weff ----------------
__global__ __launch_bounds__(256) void k_rew2(const float* __restrict__ ctx,
                                              float* __restrict__ outp){
    __shared__ float As[16][33];
    __shared__ float Bs[16][256];
    const int bm   = blockIdx.x >> 1;
    const int col0 = (blockIdx.x & 1) << 8;
    const int t  = threadIdx.x;
    const int tc = t & 63;
    const int tr = t >> 6;
    float acc[8][4];
#pragma unroll
    for (int i = 0; i < 8; i++)
#pragma unroll
        for (int j = 0; j < 4; j++) acc[i][j] = 0.f;

    const float* cpb = ctx + (long)bm*Kn*Hn;

    for (int k0 = 0; k0 < Hn; k0 += 16){
        const int kt = k0 >> 5;
        const int kin0 = k0 & 31;
#pragma unroll
        for (int i = t; i < 512; i += 256){
            int r = i >> 4, kk = i & 15;
            As[kk][r] = (r < Kn) ? cpb[r*Hn + k0 + kk] : 0.f;
        }
#pragma unroll
        for (int p = 0; p < 4; p++){
            int kk = (t >> 6) + p*4;          // 0..15
            int cc = (t & 63)*4;              // 0..252
            int col = col0 + cc;
            int nt = col >> 6, cin = col & 63;
            const float* src = g_weff + ((long)(kt*8 + nt)*BMn + bm)*2048
                             + (kin0 + kk)*64 + cin;
            *(float4*)&Bs[kk][cc] = *(const float4*)src;
        }
        __syncthreads();
#pragma unroll
        for (int kk = 0; kk < 16; kk++){
            float4 b = *(float4*)&Bs[kk][tc*4];
            float a[8];
#pragma unroll
            for (int i = 0; i < 8; i++) a[i] = As[kk][tr*8 + i];
#pragma unroll
            for (int i = 0; i < 8; i++){
                acc[i][0] += a[i]*b.x;
                acc[i][1] += a[i]*b.y;
                acc[i][2] += a[i]*b.z;
                acc[i][3] += a[i]*b.w;
            }
        }
        __syncthreads();
    }
    float4 be = *(const float4*)&g_beff[bm*Hn + col0 + tc*4];
#pragma unroll
    for (int i = 0; i < 8; i++){
        int r = tr*8 + i;
        if (r < Kn){
            float4 v;
            v.x = acc[i][0] + be.x;
            v.y = acc[i][1] + be.y;
            v.z = acc[i][2] + be.z;
            v.w = acc[i][3] + be.w;
            *(float4*)&outp[((long)(bm*Kn + r))*Hn + col0 + tc*4] = v;
        }
    }
}

// ---------------- host launcher ----------------
extern "C" void kernel_launch(void* const* d_in, const int* in_sizes, int n_in,
                              void* d_out, int out_size){
    const float* ctx  = (const float*)d_in[0];
    const float* sent = (const float*)d_in[1];
    const int*   aidx = (const int*)d_in[2];
    const void*  mask = (const void*)d_in[3];
    const float* Wtr  = (const float*)d_in[4];
    const float* btr  = (const float*)d_in[5];
    const float* Wind = (const float*)d_in[6];
    const float* bind = (const float*)d_in[7];
    const float* Wq   = (const float*)d_in[8];
    const float* Wk   = (const float*)d_in[9];
    const float* Wv   = (const float*)d_in[10];
    const float* Wq2  = (const float*)d_in[11];
    const float* Wk2  = (const float*)d_in[12];
    const float* sla  = (const float*)d_in[13];
    const float* sle  = (const float*)d_in[14];
    const float* wsh  = (const float*)d_in[15];
    const float* bsh  = (const float*)d_in[16];
    const float* wfin = (const float*)d_in[17];
    const float* bfin = (const float*)d_in[18];
    float* out = (float*)d_out;

    void* tmp;
    cudaGetSymbolAddress(&tmp, g_pred_s); float* pred_s = (float*)tmp;
    cudaGetSymbolAddress(&tmp, g_ind_s);  float* ind_s  = (float*)tmp;

    const bool big_out = (out_size >= (BMKn + BMKn*Hn + BMKn*Sn + Bn*Sn*Mn*2));
    float *p_final = out;
    float *p_rew  = big_out ? out + BMKn : nullptr;
    float *p_pred = big_out ? out + BMKn + BMKn*Hn : pred_s;
    float *p_ind  = big_out ? out + BMKn + BMKn*Hn + BMKn*Sn : ind_s;

    cudaFuncSetAttribute(k_stage2, cudaFuncAttributeMaxDynamicSharedMemorySize, 90*1024);

    int dev = 0; cudaGetDevice(&dev);
    int sms = 148;
    cudaDeviceGetAttribute(&sms, cudaDevAttrMultiProcessorCount, dev);
    int nb = 0;
    cudaOccupancyMaxActiveBlocksPerMultiprocessor(&nb, k_mega, 256, 0);
    if (nb < 4) nb = 4;
    int grid = nb * sms;

    k_mega<<<grid, 256>>>(sent, aidx, mask, ctx, Wtr, btr, wsh, bsh, wfin,
                          Wq, Wv, Wq2, Wk, Wk2, sla, sle, p_pred);

    size_t sm2 = (size_t)(Kn*CP + NHn*CP + Hn + NHn*32 + 16)*sizeof(float);
    k_stage2<<<Bn*Sn*Mn, 256, sm2>>>(ctx, mask, Wind, bind, p_ind);

    k_attn_beff<<<BMn, 512>>>(btr);

    if (big_out){
        k_weff<<<dim3(16, 8), 256>>>(Wtr);
        k_rew2<<<BMn*2, 256>>>(ctx, p_rew);
    }
    k_finalv<<<(BMKn + 255)/256, 256>>>(bfin, p_final);
}

// round 16
// speedup vs baseline: 1.1427x; 1.0957x over previous
#include <cuda_runtime.h>
#include <cuda_fp16.h>
#include <math.h>

#define Bn   64
#define Mn   10
#define Kn   30
#define Hn   512
#define Nn   128
#define Sn   5
#define NHn  8
#define DHn  64
#define BMn  640
#define BMKn 19200
#define HH   (Hn*Hn)

#define NEG_BIG (-1.0e9f)
#define NEG_INF (-3.402823e38f)

// ---------------- scratch ----------------
__device__ float g_wal  [BMn*Hn];
__device__ float g_sentT[Bn*Hn*Nn];
__device__ float g_WkT  [Sn*HH];
__device__ float g_Wk2T [Sn*HH];
__device__ float g_q1   [Bn*Sn*Mn*Hn];
__device__ float g_t    [Bn*Sn*Mn*NHn*Hn];
__device__ float g_sc1  [Bn*Sn*Mn*NHn*Nn];
__device__ float g_u    [Bn*Sn*Mn*NHn*Hn];
__device__ float g_ctx1 [Bn*Sn*Mn*Hn];
__device__ float g_q2   [Bn*Sn*Mn*Hn];
__device__ float g_r    [Bn*Sn*Mn*NHn*Hn];
__device__ float g_us   [Sn*Hn];
__device__ float g_vs   [Sn*Hn];
__device__ float g_ds   [Sn];
__device__ float g_es   [Sn];
__device__ float g_indp [BMn*Sn];
__device__ float g_margin[BMn*Sn];
__device__ float g_attn [BMn*Sn];
__device__ float g_beff [BMn*Hn];
__device__ float g_fdot [BMKn*Sn];
__device__ int   g_mask_mode;
// weff in fp16, tile-blocked: [tile(kt*8+nt)][bm][kk(32)*64 + c]
__device__ __half g_weffh [BMn*(long)HH];
__device__ float g_pred_s[BMKn*Sn];
__device__ float g_ind_s [Bn*Sn*Mn*2];
__device__ unsigned g_bar_count = 0;
__device__ unsigned g_bar_gen   = 0;

// ---------------- warp helpers ----------------
__device__ __forceinline__ float wsum(float v){
#pragma unroll
    for (int o = 16; o; o >>= 1) v += __shfl_xor_sync(0xffffffffu, v, o);
    return v;
}
__device__ __forceinline__ float wmaxf(float v){
#pragma unroll
    for (int o = 16; o; o >>= 1) v = fmaxf(v, __shfl_xor_sync(0xffffffffu, v, o));
    return v;
}

__device__ __forceinline__ bool mask_padded(const void* m, int idx){
    int mode = g_mask_mode;
    if (mode == 0) return ((const unsigned char*)m)[idx] != 0;
    if (mode == 1) return ((const int*)m)[idx] != 0;
    return ((const float*)m)[idx] != 0.f;
}

// ---------------- software grid barrier ----------------
__device__ __forceinline__ void grid_barrier(){
    __syncthreads();
    if (threadIdx.x == 0){
        __threadfence();
        unsigned gen = atomicAdd(&g_bar_gen, 0u);
        unsigned t = atomicAdd(&g_bar_count, 1u);
        if (t == gridDim.x - 1u){
            atomicExch(&g_bar_count, 0u);
            __threadfence();
            atomicAdd(&g_bar_gen, 1u);
        } else {
            while (atomicAdd(&g_bar_gen, 0u) == gen) __nanosleep(64);
        }
        __threadfence();
    }
    __syncthreads();
}

// ---------------- op functors ----------------
struct OpQ1 {
    const float* Wq; const float* slice;
    static constexpr int ROWS = BMn, KD = Hn;
    __device__ float loadA(int z, int row, int k) const {
        return g_wal[row*Hn + k] + slice[z*Hn + k];
    }
    __device__ float loadB(int z, int k, int n) const { return Wq[(long)z*HH + k*Hn + n]; }
    __device__ void store(int z, int row, int col, float v) const {
        int b = row/Mn, m = row - b*Mn;
        g_q1[((b*Sn + z)*Mn + m)*Hn + col] = v;
    }
};
struct OpT {
    static constexpr int ROWS = BMn, KD = DHn;
    __device__ float loadA(int z, int row, int k) const {
        int s = z >> 3, a = z & 7; int b = row/Mn, m = row - b*Mn;
        return g_q1[((b*Sn + s)*Mn + m)*Hn + a*DHn + k];
    }
    __device__ float loadB(int z, int k, int n) const {
        int s = z >> 3, a = z & 7;
        return g_WkT[(long)s*HH + (a*DHn + k)*Hn + n];
    }
    __device__ void store(int z, int row, int col, float v) const {
        int s = z >> 3, a = z & 7; int b = row/Mn, m = row - b*Mn;
        g_t[(((b*Sn + s)*Mn + m)*NHn + a)*Hn + col] = v;
    }
};
struct OpR {
    static constexpr int ROWS = BMn, KD = DHn;
    __device__ float loadA(int z, int row, int k) const {
        int s = z >> 3, a = z & 7; int b = row/Mn, m = row - b*Mn;
        return g_q2[((b*Sn + s)*Mn + m)*Hn + a*DHn + k];
    }
    __device__ float loadB(int z, int k, int n) const {
        int s = z >> 3, a = z & 7;
        return g_Wk2T[(long)s*HH + (a*DHn + k)*Hn + n];
    }
    __device__ void store(int z, int row, int col, float v) const {
        int s = z >> 3, a = z & 7; int b = row/Mn, m = row - b*Mn;
        g_r[(((b*Sn + s)*Mn + m)*NHn + a)*Hn + col] = v;
    }
};
struct OpSC1 {
    static constexpr int ROWS = 400, KD = Hn;
    __device__ float loadA(int z, int row, int k) const { return g_t[((long)z*400 + row)*Hn + k]; }
    __device__ float loadB(int z, int k, int n) const { return g_sentT[((long)z*Hn + k)*Nn + n]; }
    __device__ void store(int z, int row, int col, float v) const {
        g_sc1[((long)z*400 + row)*Nn + col] = 0.125f * v;
    }
};
struct OpU {
    const float* sent;
    static constexpr int ROWS = 400, KD = Nn;
    __device__ float loadA(int z, int row, int k) const { return g_sc1[((long)z*400 + row)*Nn + k]; }
    __device__ float loadB(int z, int k, int n) const { return sent[((long)z*Nn + k)*Hn + n]; }
    __device__ void store(int z, int row, int col, float v) const {
        g_u[((long)z*400 + row)*Hn + col] = v;
    }
};
struct OpCTX1 {
    const float* Wv;
    static constexpr int ROWS = BMn, KD = Hn;
    __device__ float loadA(int z, int row, int k) const {
        int s = z >> 3, a = z & 7; int b = row/Mn, m = row - b*Mn;
        return g_u[(((b*Sn + s)*Mn + m)*NHn + a)*Hn + k];
    }
    __device__ float loadB(int z, int k, int n) const {
        int s = z >> 3, a = z & 7;
        return Wv[(long)s*HH + k*Hn + a*DHn + n];
    }
    __device__ void store(int z, int row, int col, float v) const {
        int s = z >> 3, a = z & 7; int b = row/Mn, m = row - b*Mn;
        g_ctx1[((b*Sn + s)*Mn + m)*Hn + a*DHn + col] = v;
    }
};
struct OpQ2 {
    const float* Wq2; const float* slice;
    static constexpr int ROWS = BMn, KD = Hn;
    __device__ float loadA(int z, int row, int k) const {
        int b = row/Mn, m = row - b*Mn;
        return g_ctx1[((b*Sn + z)*Mn + m)*Hn + k] + slice[z*Hn + k];
    }
    __device__ float loadB(int z, int k, int n) const { return Wq2[(long)z*HH + k*Hn + n]; }
    __device__ void store(int z, int row, int col, float v) const {
        int b = row/Mn, m = row - b*Mn;
        g_q2[((b*Sn + z)*Mn + m)*Hn + col] = v;
    }
};

// ---------------- tile device functions ----------------
template <class OP>
__device__ void tile_gemm128(const OP& op, int row0, int col0, int z, float* sh, int t){
    float* As = sh;
    float* Bs = sh + 1040;
    const int tr = t >> 5, tc = t & 31;
    float acc[8][4];
#pragma unroll
    for (int i = 0; i < 8; i++)
#pragma unroll
        for (int j = 0; j < 4; j++) acc[i][j] = 0.f;

    for (int k0 = 0; k0 < OP::KD; k0 += 16){
#pragma unroll
        for (int i = 0; i < 4; i++){
            int idx = t + i*256;
            int rr = idx >> 4, kk = idx & 15;
            int row = row0 + rr;
            As[kk*65 + rr] = (row < OP::ROWS) ? op.loadA(z, row, k0 + kk) : 0.f;
        }
#pragma unroll
        for (int i = 0; i < 8; i++){
            int idx = t + i*256;
            int kk = idx >> 7, nn = idx & 127;
            Bs[kk*128 + nn] = op.loadB(z, k0 + kk, col0 + nn);
        }
        __syncthreads();
#pragma unroll
        for (int kk = 0; kk < 16; kk++){
            float4 b = *(const float4*)&Bs[kk*128 + tc*4];
            float a[8];
#pragma unroll
            for (int i = 0; i < 8; i++) a[i] = As[kk*65 + tr*8 + i];
#pragma unroll
            for (int i = 0; i < 8; i++){
                acc[i][0] += a[i]*b.x;
                acc[i][1] += a[i]*b.y;
                acc[i][2] += a[i]*b.z;
                acc[i][3] += a[i]*b.w;
            }
        }
        __syncthreads();
    }
#pragma unroll
    for (int i = 0; i < 8; i++){
        int row = row0 + tr*8 + i;
        if (row >= OP::ROWS) continue;
#pragma unroll
        for (int j = 0; j < 4; j++) op.store(z, row, col0 + tc*4 + j, acc[i][j]);
    }
    __syncthreads();
}

template <class OP>
__device__ void tile_gemm64(const OP& op, int row0, int col0, int z, float* sh, int t){
    float* As = sh;
    float* Bs = sh + 1040;
    const int tr = t >> 5, tc = t & 31;
    float acc[8][2];
#pragma unroll
    for (int i = 0; i < 8; i++){ acc[i][0] = 0.f; acc[i][1] = 0.f; }

    for (int k0 = 0; k0 < OP::KD; k0 += 16){
#pragma unroll
        for (int i = 0; i < 4; i++){
            int idx = t + i*256;
            int rr = idx >> 4, kk = idx & 15;
            int row = row0 + rr;
            As[kk*65 + rr] = (row < OP::ROWS) ? op.loadA(z, row, k0 + kk) : 0.f;
        }
#pragma unroll
        for (int i = 0; i < 4; i++){
            int idx = t + i*256;
            int kk = idx >> 6, nn = idx & 63;
            Bs[kk*64 + nn] = op.loadB(z, k0 + kk, col0 + nn);
        }
        __syncthreads();
#pragma unroll
        for (int kk = 0; kk < 16; kk++){
            float2 b = *(const float2*)&Bs[kk*64 + tc*2];
            float a[8];
#pragma unroll
            for (int i = 0; i < 8; i++) a[i] = As[kk*65 + tr*8 + i];
#pragma unroll
            for (int i = 0; i < 8; i++){
                acc[i][0] += a[i]*b.x;
                acc[i][1] += a[i]*b.y;
            }
        }
        __syncthreads();
    }
#pragma unroll
    for (int i = 0; i < 8; i++){
        int row = row0 + tr*8 + i;
        if (row >= OP::ROWS) continue;
        op.store(z, row, col0 + tc*2, acc[i][0]);
        op.store(z, row, col0 + tc*2 + 1, acc[i][1]);
    }
    __syncthreads();
}

__device__ void tile_transpose(const float* in, float* out, int R, int C,
                               int c0, int r0, float* sh, int t){
    float* tile = sh;
    int tx = t & 31, ty = t >> 5;
#pragma unroll
    for (int i = 0; i < 32; i += 8){
        int r = r0 + ty + i, c = c0 + tx;
        tile[(ty + i)*33 + tx] = (r < R && c < C) ? in[(long)r*C + c] : 0.f;
    }
    __syncthreads();
#pragma unroll
    for (int i = 0; i < 32; i += 8){
        int c = c0 + ty + i, r = r0 + tx;
        if (c < C && r < R) out[(long)c*R + r] = tile[tx*33 + ty + i];
    }
    __syncthreads();
}

__device__ void tile_wal(const float* sent, const int* aidx, int bm, int t){
    int b = bm / Mn;
    int idx = aidx[bm];
    const float* src = sent + ((long)b*Nn + idx)*Hn;
#pragma unroll
    for (int i = 0; i < 2; i++) g_wal[bm*Hn + t + i*256] = src[t + i*256];
}

__device__ void tile_us(const float* Wt, const float* btr, const float* wsh,
                        const float* bsh, const float* wfin, int s, int t){
    int w = t >> 5, lane = t & 31;
    for (int h = w; h < Hn; h += 8){
        const float* wrow = Wt + ((long)s*Hn + h)*Hn;
        float aU = 0.f, aV = 0.f;
        for (int g = lane; g < Hn; g += 32){
            float x = wrow[g];
            aU += x*wsh[g];
            aV += x*wfin[g];
        }
        aU = wsum(aU); aV = wsum(aV);
        if (lane == 0){ g_us[s*Hn + h] = aU; g_vs[s*Hn + h] = aV; }
    }
    if (w == 0){
        float dU = 0.f, dV = 0.f;
        for (int h = lane; h < Hn; h += 32){
            float b = btr[s*Hn + h];
            dU += b*wsh[h];
            dV += b*wfin[h];
        }
        dU = wsum(dU); dV = wsum(dV);
        if (lane == 0){ g_ds[s] = dU + bsh[0]; g_es[s] = dV; }
    }
}

__device__ void tile_maskdetect(const unsigned char* m, float* sh, int t){
    int* si = (int*)sh;
    if (t == 0){ si[0] = 0; si[1] = 0; }
    __syncthreads();
    int c1 = 0, c2 = 0;
    for (int i = t; i < BMKn; i += 256){
        unsigned char v = m[i];
        if (v > 1) c2++;
        else if (v == 1 && (i & 3)) c1++;
    }
    atomicAdd(&si[0], c1);
    atomicAdd(&si[1], c2);
    __syncthreads();
    if (t == 0) g_mask_mode = (si[1] > 0) ? 2 : ((si[0] > 0) ? 0 : 1);
    __syncthreads();
}

__device__ void tile_predg(const float* ctx, float* pred, int row0, float* sh, int t){
    for (int i = t; i < 5120; i += 256)
        sh[i] = (i < 2560) ? g_us[i] : g_vs[i - 2560];
    __syncthreads();
    int w = t >> 5, lane = t & 31;
    int rbase = row0 + w*32;
#pragma unroll 1
    for (int i = 0; i < 32; i++){
        int r = rbase + i;
        const float* cp = ctx + (long)r*Hn;
        float a[16];
#pragma unroll
        for (int j = 0; j < 16; j++) a[j] = cp[lane + 32*j];
#pragma unroll
        for (int d = 0; d < 10; d++){
            const float* vv = sh + d*512;
            float acc = 0.f;
#pragma unroll
            for (int j = 0; j < 16; j++) acc += a[j]*vv[lane + 32*j];
            acc = wsum(acc);
            if (lane == 0){
                if (d < Sn) pred[r*Sn + d] = acc + g_ds[d];
                else        g_fdot[r*Sn + (d - Sn)] = acc + g_es[d - Sn];
            }
        }
    }
    __syncthreads();
}

__device__ void tile_margin(const float* pred, const void* mask, int bm, int t){
    int w = t >> 5, k = t & 31;
    if (w >= Sn) return;
    bool act = (k < Kn);
    float logit = NEG_BIG;
    if (act){
        float pv = pred[(bm*Kn + k)*Sn + w];
        logit = mask_padded(mask, bm*Kn + k) ? NEG_BIG : pv;
    }
    float mx = wmaxf(act ? logit : NEG_INF);
    float e = act ? expf(logit - mx) : 0.f;
    float sm = wsum(e);
    float lse = logf(sm);
    float conf = act ? (logit - mx - lse) : NEG_INF;
    float v = conf; int idx = k;
#pragma unroll
    for (int o = 16; o; o >>= 1){
        float v2 = __shfl_xor_sync(0xffffffffu, v, o);
        int   i2 = __shfl_xor_sync(0xffffffffu, idx, o);
        if (v2 > v || (v2 == v && i2 < idx)){ v = v2; idx = i2; }
    }
    float c2 = (act && k != idx) ? conf : NEG_INF;
    float v2m = wmaxf(c2);
    if (k == 0) g_margin[bm*Sn + w] = (v - v2m) / (v + v2m);
}

__device__ void tile_sm1(int grp, int t){
    int w = t >> 5, lane = t & 31;
#pragma unroll
    for (int rr = 0; rr < 2; rr++){
        long row = (long)grp*16 + w + rr*8;
        float v[4]; float mx = NEG_INF;
#pragma unroll
        for (int i = 0; i < 4; i++){ v[i] = g_sc1[row*Nn + lane + 32*i]; mx = fmaxf(mx, v[i]); }
        mx = wmaxf(mx);
        float sm = 0.f;
#pragma unroll
        for (int i = 0; i < 4; i++){ v[i] = expf(v[i] - mx); sm += v[i]; }
        sm = wsum(sm);
        float inv = 1.f/sm;
#pragma unroll
        for (int i = 0; i < 4; i++) g_sc1[row*Nn + lane + 32*i] = v[i]*inv;
    }
}

// ---------------- persistent megakernel ----------------
__global__ __launch_bounds__(256, 4) void k_mega(
    const float* __restrict__ sent, const int* __restrict__ aidx,
    const void* __restrict__ mask, const float* __restrict__ ctx,
    const float* __restrict__ Wt, const float* __restrict__ btr,
    const float* __restrict__ wsh, const float* __restrict__ bsh,
    const float* __restrict__ wfin, const float* __restrict__ Wq,
    const float* __restrict__ Wv, const float* __restrict__ Wq2,
    const float* __restrict__ Wk, const float* __restrict__ Wk2,
    const float* __restrict__ sla, const float* __restrict__ sle,
    float* __restrict__ pred)
{
    __shared__ float sh[5200];
    const int t = threadIdx.x;
    const unsigned NB = gridDim.x;

    // S0
    for (unsigned tt = blockIdx.x; tt < 7302u; tt += NB){
        if (tt < 1280u){
            int cx = tt & 15, cy = (tt >> 4) & 15, z = tt >> 8;
            tile_transpose(Wk + (long)z*HH, g_WkT + (long)z*HH, Hn, Hn, cx*32, cy*32, sh, t);
        } else if (tt < 2560u){
            unsigned u = tt - 1280u;
            int cx = u & 15, cy = (u >> 4) & 15, z = u >> 8;
            tile_transpose(Wk2 + (long)z*HH, g_Wk2T + (long)z*HH, Hn, Hn, cx*32, cy*32, sh, t);
        } else if (tt < 6656u){
            unsigned u = tt - 2560u;
            int cx = u & 15, cy = (u >> 4) & 3, z = u >> 6;
            tile_transpose(sent + (long)z*Nn*Hn, g_sentT + (long)z*Hn*Nn, Nn, Hn, cx*32, cy*32, sh, t);
        } else if (tt < 7296u){
            tile_wal(sent, aidx, (int)(tt - 6656u), t);
        } else if (tt < 7301u){
            tile_us(Wt, btr, wsh, bsh, wfin, (int)(tt - 7296u), t);
        } else {
            tile_maskdetect((const unsigned char*)mask, sh, t);
        }
    }
    grid_barrier();

    // S1: predg (75) + Q1 (200)
    {
        OpQ1 op{Wq, sla};
        for (unsigned tt = blockIdx.x; tt < 275u; tt += NB){
            if (tt < 75u) tile_predg(ctx, pred, (int)tt*256, sh, t);
            else {
                unsigned q = tt - 75u;
                tile_gemm128(op, (int)(q % 10u)*64, (int)((q/10u) % 4u)*128, (int)(q/40u), sh, t);
            }
        }
    }
    grid_barrier();

    // S2: margin (640) + T (1600)
    {
        OpT op{};
        for (unsigned tt = blockIdx.x; tt < 2240u; tt += NB){
            if (tt < 640u) tile_margin(pred, mask, (int)tt, t);
            else {
                unsigned q = tt - 640u;
                tile_gemm128(op, (int)(q % 10u)*64, (int)((q/10u) % 4u)*128, (int)(q/40u), sh, t);
            }
        }
    }
    grid_barrier();

    // S3: SC1 (448)
    {
        OpSC1 op{};
        for (unsigned tt = blockIdx.x; tt < 448u; tt += NB)
            tile_gemm128(op, (int)(tt % 7u)*64, 0, (int)(tt/7u), sh, t);
    }
    grid_barrier();

    // S4: sm1
    for (unsigned tt = blockIdx.x; tt < 1600u; tt += NB) tile_sm1((int)tt, t);
    grid_barrier();

    // S5: U
    {
        OpU op{sent};
        for (unsigned tt = blockIdx.x; tt < 1792u; tt += NB)
            tile_gemm128(op, (int)(tt % 7u)*64, (int)((tt/7u) % 4u)*128, (int)(tt/28u), sh, t);
    }
    grid_barrier();

    // S6: CTX1
    {
        OpCTX1 op{Wv};
        for (unsigned tt = blockIdx.x; tt < 400u; tt += NB)
            tile_gemm64(op, (int)(tt % 10u)*64, 0, (int)(tt/10u), sh, t);
    }
    grid_barrier();

    // S7: Q2
    {
        OpQ2 op{Wq2, sle};
        for (unsigned tt = blockIdx.x; tt < 200u; tt += NB)
            tile_gemm128(op, (int)(tt % 10u)*64, (int)((tt/10u) % 4u)*128, (int)(tt/40u), sh, t);
    }
    grid_barrier();

    // S8: R
    {
        OpR op{};
        for (unsigned tt = blockIdx.x; tt < 1600u; tt += NB)
            tile_gemm128(op, (int)(tt % 10u)*64, (int)((tt/10u) % 4u)*128, (int)(tt/40u), sh, t);
    }
}

// ---------------- stage2 (CP=524: conflict-free LDS.128 rows) ----------------
#define CP 524
__global__ void k_stage2(const float* __restrict__ ctx, const void* __restrict__ mask,
                         const float* __restrict__ Wind, const float* __restrict__ bind,
                         float* __restrict__ ind_out){
    extern __shared__ float smem[];
    float* ctx_sh   = smem;
    float* r_sh     = ctx_sh + Kn*CP;
    float* alias_sh = r_sh + NHn*CP;
    float* ew_sh    = alias_sh + Hn;
    float* red      = ew_sh + NHn*32;

    int blk = blockIdx.x;
    int m = blk % Mn; int bs = blk / Mn; int s = bs % Sn; int b = bs / Sn;
    int bm = b*Mn + m;
    int tid = threadIdx.x;
    for (int i = tid; i < Kn*Hn; i += 256){
        int r = i >> 9, h = i & 511;
        ctx_sh[r*CP + h] = ctx[((long)bm*Kn + r)*Hn + h];
    }
    for (int i = tid; i < NHn*Hn; i += 256){
        int a = i >> 9, h = i & 511;
        r_sh[a*CP + h] = g_r[((long)blk*NHn + a)*Hn + h];
    }
    __syncthreads();

    int a = tid >> 5, k = tid & 31;
    {
        bool act = (k < Kn);
        float acc = 0.f;
        if (act){
            const float4* cp = reinterpret_cast<const float4*>(ctx_sh + k*CP);
            const float4* rp = reinterpret_cast<const float4*>(r_sh + a*CP);
            for (int h4 = 0; h4 < Hn/4; h4++){
                float4 c = cp[h4], rr = rp[h4];
                acc += c.x*rr.x + c.y*rr.y + c.z*rr.z + c.w*rr.w;
            }
        }
        float x = NEG_BIG;
        if (act) x = mask_padded(mask, bm*Kn + k) ? NEG_BIG : acc*0.125f;
        float mx = wmaxf(act ? x : NEG_INF);
        float e = act ? expf(x - mx) : 0.f;
        float sv = wsum(e);
        if (act) ew_sh[a*32 + k] = e/sv;
    }
    __syncthreads();
    for (int g = tid; g < Hn; g += 256){
        int ah = g >> 6;
        float acc = 0.f;
#pragma unroll
        for (int kk = 0; kk < Kn; kk++) acc += ew_sh[ah*32 + kk]*ctx_sh[kk*CP + g];
        alias_sh[g] = acc;
    }
    __syncthreads();
    float p0 = 0.f, p1 = 0.f;
    for (int g = tid; g < Hn; g += 256){
        float av = alias_sh[g];
        p0 += av*Wind[(s*Hn + g)*2 + 0];
        p1 += av*Wind[(s*Hn + g)*2 + 1];
    }
    p0 = wsum(p0); p1 = wsum(p1);
    if ((tid & 31) == 0){ red[(tid >> 5)*2] = p0; red[(tid >> 5)*2 + 1] = p1; }
    __syncthreads();
    if (tid == 0){
        float i0 = 0.f, i1 = 0.f;
        for (int wv = 0; wv < 8; wv++){ i0 += red[wv*2]; i1 += red[wv*2 + 1]; }
        i0 += bind[s*2 + 0]; i1 += bind[s*2 + 1];
        ind_out[blk*2 + 0] = i0;
        ind_out[blk*2 + 1] = i1;
        float mx = fmaxf(i0, i1);
        float lse = mx + logf(expf(i0 - mx) + expf(i1 - mx));
        g_indp[bm*Sn + s] = i1 - lse;
    }
}

__global__ void k_attn_beff(const float* __restrict__ btr){
    __shared__ float at[Sn];
    int bm = blockIdx.x, t = threadIdx.x;
    if (t < 32){
        int s = t;
        bool act = (s < Sn);
        float x = act ? (g_indp[bm*Sn + s] + g_margin[bm*Sn + s])*4.0f : NEG_INF;
        float mx = wmaxf(x);
        float e = act ? expf(x - mx) : 0.f;
        float sm = wsum(e);
        if (act){ float v = e/sm; g_attn[bm*Sn + s] = v; at[s] = v; }
    }
    __syncthreads();
    float acc = 0.f;
#pragma unroll
    for (int s = 0; s < Sn; s++) acc += at[s]*btr[s*Hn + t];
    g_beff[bm*Hn + t] = acc;
}

__global__ void k_finalv(const float* __restrict__ bfin, float* __restrict__ out){
    int i = blockIdx.x*256 + threadIdx.x;
    if (i >= BMKn) return;
    int bm = i / Kn;
    float acc = bfin[0];
#pragma unroll
    for (int s = 0; s < Sn; s++) acc += g_attn[bm*Sn + s]*g_fdot[i*Sn + s];
    out[i] = acc;
}

// ---------------- REW phase 1: Weff in fp16, tile-blocked contiguous stream --------
// Each thread packs 8 outputs to 4xhalf2 = one 16B store per bm iteration.
__global__ __launch_bounds__(256) void k_weff(const float* __restrict__ Wt){
    __shared__ float at[BMn*Sn];
    const int kt = blockIdx.x, nt = blockIdx.y;
    const int k0 = kt*32, n0 = nt*64;
    const int t = threadIdx.x;
    for (int i = t; i < BMn*Sn; i += 256) at[i] = g_attn[i];
    const int kk = t >> 3, cg = t & 7;
    float w[Sn][8];
#pragma unroll
    for (int s = 0; s < Sn; s++){
        *(float4*)&w[s][0] = *(const float4*)&Wt[((long)s*Hn + k0 + kk)*Hn + n0 + cg*8];
        *(float4*)&w[s][4] = *(const float4*)&Wt[((long)s*Hn + k0 + kk)*Hn + n0 + cg*8 + 4];
    }
    __syncthreads();
    __half* dst0 = g_weffh + ((long)(kt*8 + nt)*BMn)*2048 + kk*64 + cg*8;
    for (int bm = 0; bm < BMn; bm++){
        float a0 = at[bm*Sn+0], a1 = at[bm*Sn+1], a2 = at[bm*Sn+2],
              a3 = at[bm*Sn+3], a4 = at[bm*Sn+4];
        __half2 o[4];
#pragma unroll
        for (int j = 0; j < 4; j++){
            float v0 = a0*w[0][2*j]   + a1*w[1][2*j]   + a2*w[2][2*j]
                     + a3*w[3][2*j]   + a4*w[4][2*j];
            float v1 = a0*w[0][2*j+1] + a1*w[1][2*j+1] + a2*w[2][2*j+1]
                     + a3*w[3][2*j+1] + a4*w[4][2*j+1];
            o[j] = __floats2half2_rn(v0, v1);
        }
        *(uint4*)(dst0 + (long)bm*2048) = *(uint4*)o;
    }
}

// ---------------- REW phase 2: reads fp16 tile-blocked weff ----------------
__global__ __launch_bounds__(256) void k_rew2(const float* __restrict__ ctx,
                                              float* __restrict__ outp){
    __shared__ float As[16][33];
    __shared__ float Bs[16][256];
    const int bm   = blockIdx.x >> 1;
    const int col0 = (blockIdx.x & 1) << 8;
    const int t  = threadIdx.x;
    const int tc = t & 63;
    const int tr = t >> 6;
    float acc[8][4];
#pragma unroll
    for (int i = 0; i < 8; i++)
#pragma unroll
        for (int j = 0; j < 4; j++) acc[i][j] = 0.f;

    const float* cpb = ctx + (long)bm*Kn*Hn;

    for (int k0 = 0; k0 < Hn; k0 += 16){
        const int kt = k0 >> 5;
        const int kin0 = k0 & 31;
#pragma unroll
        for (int i = t; i < 512; i += 256){
            int r = i >> 4, kk = i & 15;
            As[kk][r] = (r < Kn) ? cpb[r*Hn + k0 + kk] : 0.f;
        }
        // B tile: 16x256 halves; each thread loads 8 halves (16B) and converts
#pragma unroll
        for (int p = 0; p < 2; p++){
            int idx = t + p*256;            // 0..511
            int kk = idx >> 5;              // 0..15
            int c8 = (idx & 31)*8;          // 0..248
            int col = col0 + c8;
            int nt = col >> 6, cin = col & 63;
            const __half* src = g_weffh + ((long)(kt*8 + nt)*BMn + bm)*2048
                              + (kin0 + kk)*64 + cin;
            uint4 hv = *(const uint4*)src;
            const __half2* hp = (const __half2*)&hv;
            float2 f0 = __half22float2(hp[0]);
            float2 f1 = __half22float2(hp[1]);
            float2 f2 = __half22float2(hp[2]);
            float2 f3 = __half22float2(hp[3]);
            float4 lo = {f0.x, f0.y, f1.x, f1.y};
            float4 hi = {f2.x, f2.y, f3.x, f3.y};
            *(float4*)&Bs[kk][c8]     = lo;
            *(float4*)&Bs[kk][c8 + 4] = hi;
        }
        __syncthreads();
#pragma unroll
        for (int kk = 0; kk < 16; kk++){
            float4 b = *(float4*)&Bs[kk][tc*4];
            float a[8];
#pragma unroll
            for (int i = 0; i < 8; i++) a[i] = As[kk][tr*8 + i];
#pragma unroll
            for (int i = 0; i < 8; i++){
                acc[i][0] += a[i]*b.x;
                acc[i][1] += a[i]*b.y;
                acc[i][2] += a[i]*b.z;
                acc[i][3] += a[i]*b.w;
            }
        }
        __syncthreads();
    }
    float4 be = *(const float4*)&g_beff[bm*Hn + col0 + tc*4];
#pragma unroll
    for (int i = 0; i < 8; i++){
        int r = tr*8 + i;
        if (r < Kn){
            float4 v;
            v.x = acc[i][0] + be.x;
            v.y = acc[i][1] + be.y;
            v.z = acc[i][2] + be.z;
            v.w = acc[i][3] + be.w;
            *(float4*)&outp[((long)(bm*Kn + r))*Hn + col0 + tc*4] = v;
        }
    }
}

// ---------------- host launcher ----------------
extern "C" void kernel_launch(void* const* d_in, const int* in_sizes, int n_in,
                              void* d_out, int out_size){
    const float* ctx  = (const float*)d_in[0];
    const float* sent = (const float*)d_in[1];
    const int*   aidx = (const int*)d_in[2];
    const void*  mask = (const void*)d_in[3];
    const float* Wtr  = (const float*)d_in[4];
    const float* btr  = (const float*)d_in[5];
    const float* Wind = (const float*)d_in[6];
    const float* bind = (const float*)d_in[7];
    const float* Wq   = (const float*)d_in[8];
    const float* Wk   = (const float*)d_in[9];
    const float* Wv   = (const float*)d_in[10];
    const float* Wq2  = (const float*)d_in[11];
    const float* Wk2  = (const float*)d_in[12];
    const float* sla  = (const float*)d_in[13];
    const float* sle  = (const float*)d_in[14];
    const float* wsh  = (const float*)d_in[15];
    const float* bsh  = (const float*)d_in[16];
    const float* wfin = (const float*)d_in[17];
    const float* bfin = (const float*)d_in[18];
    float* out = (float*)d_out;

    void* tmp;
    cudaGetSymbolAddress(&tmp, g_pred_s); float* pred_s = (float*)tmp;
    cudaGetSymbolAddress(&tmp, g_ind_s);  float* ind_s  = (float*)tmp;

    const bool big_out = (out_size >= (BMKn + BMKn*Hn + BMKn*Sn + Bn*Sn*Mn*2));
    float *p_final = out;
    float *p_rew  = big_out ? out + BMKn : nullptr;
    float *p_pred = big_out ? out + BMKn + BMKn*Hn : pred_s;
    float *p_ind  = big_out ? out + BMKn + BMKn*Hn + BMKn*Sn : ind_s;

    cudaFuncSetAttribute(k_stage2, cudaFuncAttributeMaxDynamicSharedMemorySize, 90*1024);

    int dev = 0; cudaGetDevice(&dev);
    int sms = 148;
    cudaDeviceGetAttribute(&sms, cudaDevAttrMultiProcessorCount, dev);
    int nb = 0;
    cudaOccupancyMaxActiveBlocksPerMultiprocessor(&nb, k_mega, 256, 0);
    if (nb < 4) nb = 4;
    int grid = nb * sms;

    k_mega<<<grid, 256>>>(sent, aidx, mask, ctx, Wtr, btr, wsh, bsh, wfin,
                          Wq, Wv, Wq2, Wk, Wk2, sla, sle, p_pred);

    size_t sm2 = (size_t)(Kn*CP + NHn*CP + Hn + NHn*32 + 16)*sizeof(float);
    k_stage2<<<Bn*Sn*Mn, 256, sm2>>>(ctx, mask, Wind, bind, p_ind);

    k_attn_beff<<<BMn, 512>>>(btr);

    if (big_out){
        k_weff<<<dim3(16, 8), 256>>>(Wtr);
        k_rew2<<<BMn*2, 256>>>(ctx, p_rew);
    }
    k_finalv<<<(BMKn + 255)/256, 256>>>(bfin, p_final);
}

// round 17
// speedup vs baseline: 1.2147x; 1.0630x over previous
#include <cuda_runtime.h>
#include <cuda_fp16.h>
#include <math.h>

#define Bn   64
#define Mn   10
#define Kn   30
#define Hn   512
#define Nn   128
#define Sn   5
#define NHn  8
#define DHn  64
#define BMn  640
#define BMKn 19200
#define HH   (Hn*Hn)

#define NEG_BIG (-1.0e9f)
#define NEG_INF (-3.402823e38f)

// ---------------- scratch ----------------
__device__ float g_wal  [BMn*Hn];
__device__ float g_sentT[Bn*Hn*Nn];
__device__ float g_WkT  [Sn*HH];
__device__ float g_Wk2T [Sn*HH];
__device__ float g_q1   [Bn*Sn*Mn*Hn];
__device__ float g_t    [Bn*Sn*Mn*NHn*Hn];
__device__ float g_sc1  [Bn*Sn*Mn*NHn*Nn];
__device__ float g_u    [Bn*Sn*Mn*NHn*Hn];
__device__ float g_ctx1 [Bn*Sn*Mn*Hn];
__device__ float g_q2   [Bn*Sn*Mn*Hn];
__device__ float g_r    [Bn*Sn*Mn*NHn*Hn];
__device__ float g_us   [Sn*Hn];
__device__ float g_vs   [Sn*Hn];
__device__ float g_ds   [Sn];
__device__ float g_es   [Sn];
__device__ float g_indp [BMn*Sn];
__device__ float g_margin[BMn*Sn];
__device__ float g_attn [BMn*Sn];
__device__ float g_beff [BMn*Hn];
__device__ float g_fdot [BMKn*Sn];
__device__ int   g_mask_mode;
// weff in fp16, tile-blocked: [tile(kt*8+nt)][bm][kk(32)*64 + c]
__device__ __half g_weffh [BMn*(long)HH];
__device__ float g_pred_s[BMKn*Sn];
__device__ float g_ind_s [Bn*Sn*Mn*2];
__device__ unsigned g_bar_count = 0;
__device__ unsigned g_bar_gen   = 0;

// ---------------- warp helpers ----------------
__device__ __forceinline__ float wsum(float v){
#pragma unroll
    for (int o = 16; o; o >>= 1) v += __shfl_xor_sync(0xffffffffu, v, o);
    return v;
}
__device__ __forceinline__ float wmaxf(float v){
#pragma unroll
    for (int o = 16; o; o >>= 1) v = fmaxf(v, __shfl_xor_sync(0xffffffffu, v, o));
    return v;
}
__device__ __forceinline__ void mma_f16(float d[4], unsigned a0, unsigned a1,
                                        unsigned a2, unsigned a3,
                                        unsigned b0, unsigned b1){
    asm volatile("mma.sync.aligned.m16n8k16.row.col.f32.f16.f16.f32 "
                 "{%0,%1,%2,%3}, {%4,%5,%6,%7}, {%8,%9}, {%0,%1,%2,%3};"
                 : "+f"(d[0]), "+f"(d[1]), "+f"(d[2]), "+f"(d[3])
                 : "r"(a0), "r"(a1), "r"(a2), "r"(a3), "r"(b0), "r"(b1));
}

__device__ __forceinline__ bool mask_padded(const void* m, int idx){
    int mode = g_mask_mode;
    if (mode == 0) return ((const unsigned char*)m)[idx] != 0;
    if (mode == 1) return ((const int*)m)[idx] != 0;
    return ((const float*)m)[idx] != 0.f;
}

// ---------------- software grid barrier ----------------
__device__ __forceinline__ void grid_barrier(){
    __syncthreads();
    if (threadIdx.x == 0){
        __threadfence();
        unsigned gen = atomicAdd(&g_bar_gen, 0u);
        unsigned t = atomicAdd(&g_bar_count, 1u);
        if (t == gridDim.x - 1u){
            atomicExch(&g_bar_count, 0u);
            __threadfence();
            atomicAdd(&g_bar_gen, 1u);
        } else {
            while (atomicAdd(&g_bar_gen, 0u) == gen) __nanosleep(64);
        }
        __threadfence();
    }
    __syncthreads();
}

// ---------------- op functors ----------------
struct OpQ1 {
    const float* Wq; const float* slice;
    static constexpr int ROWS = BMn, KD = Hn;
    __device__ float loadA(int z, int row, int k) const {
        return g_wal[row*Hn + k] + slice[z*Hn + k];
    }
    __device__ float loadB(int z, int k, int n) const { return Wq[(long)z*HH + k*Hn + n]; }
    __device__ void store(int z, int row, int col, float v) const {
        int b = row/Mn, m = row - b*Mn;
        g_q1[((b*Sn + z)*Mn + m)*Hn + col] = v;
    }
};
struct OpT {
    static constexpr int ROWS = BMn, KD = DHn;
    __device__ float loadA(int z, int row, int k) const {
        int s = z >> 3, a = z & 7; int b = row/Mn, m = row - b*Mn;
        return g_q1[((b*Sn + s)*Mn + m)*Hn + a*DHn + k];
    }
    __device__ float loadB(int z, int k, int n) const {
        int s = z >> 3, a = z & 7;
        return g_WkT[(long)s*HH + (a*DHn + k)*Hn + n];
    }
    __device__ void store(int z, int row, int col, float v) const {
        int s = z >> 3, a = z & 7; int b = row/Mn, m = row - b*Mn;
        g_t[(((b*Sn + s)*Mn + m)*NHn + a)*Hn + col] = v;
    }
};
struct OpR {
    static constexpr int ROWS = BMn, KD = DHn;
    __device__ float loadA(int z, int row, int k) const {
        int s = z >> 3, a = z & 7; int b = row/Mn, m = row - b*Mn;
        return g_q2[((b*Sn + s)*Mn + m)*Hn + a*DHn + k];
    }
    __device__ float loadB(int z, int k, int n) const {
        int s = z >> 3, a = z & 7;
        return g_Wk2T[(long)s*HH + (a*DHn + k)*Hn + n];
    }
    __device__ void store(int z, int row, int col, float v) const {
        int s = z >> 3, a = z & 7; int b = row/Mn, m = row - b*Mn;
        g_r[(((b*Sn + s)*Mn + m)*NHn + a)*Hn + col] = v;
    }
};
struct OpSC1 {
    static constexpr int ROWS = 400, KD = Hn;
    __device__ float loadA(int z, int row, int k) const { return g_t[((long)z*400 + row)*Hn + k]; }
    __device__ float loadB(int z, int k, int n) const { return g_sentT[((long)z*Hn + k)*Nn + n]; }
    __device__ void store(int z, int row, int col, float v) const {
        g_sc1[((long)z*400 + row)*Nn + col] = 0.125f * v;
    }
};
struct OpU {
    const float* sent;
    static constexpr int ROWS = 400, KD = Nn;
    __device__ float loadA(int z, int row, int k) const { return g_sc1[((long)z*400 + row)*Nn + k]; }
    __device__ float loadB(int z, int k, int n) const { return sent[((long)z*Nn + k)*Hn + n]; }
    __device__ void store(int z, int row, int col, float v) const {
        g_u[((long)z*400 + row)*Hn + col] = v;
    }
};
struct OpCTX1 {
    const float* Wv;
    static constexpr int ROWS = BMn, KD = Hn;
    __device__ float loadA(int z, int row, int k) const {
        int s = z >> 3, a = z & 7; int b = row/Mn, m = row - b*Mn;
        return g_u[(((b*Sn + s)*Mn + m)*NHn + a)*Hn + k];
    }
    __device__ float loadB(int z, int k, int n) const {
        int s = z >> 3, a = z & 7;
        return Wv[(long)s*HH + k*Hn + a*DHn + n];
    }
    __device__ void store(int z, int row, int col, float v) const {
        int s = z >> 3, a = z & 7; int b = row/Mn, m = row - b*Mn;
        g_ctx1[((b*Sn + s)*Mn + m)*Hn + a*DHn + col] = v;
    }
};
struct OpQ2 {
    const float* Wq2; const float* slice;
    static constexpr int ROWS = BMn, KD = Hn;
    __device__ float loadA(int z, int row, int k) const {
        int b = row/Mn, m = row - b*Mn;
        return g_ctx1[((b*Sn + z)*Mn + m)*Hn + k] + slice[z*Hn + k];
    }
    __device__ float loadB(int z, int k, int n) const { return Wq2[(long)z*HH + k*Hn + n]; }
    __device__ void store(int z, int row, int col, float v) const {
        int b = row/Mn, m = row - b*Mn;
        g_q2[((b*Sn + z)*Mn + m)*Hn + col] = v;
    }
};

// ---------------- tile device functions ----------------
template <class OP>
__device__ void tile_gemm128(const OP& op, int row0, int col0, int z, float* sh, int t){
    float* As = sh;
    float* Bs = sh + 1040;
    const int tr = t >> 5, tc = t & 31;
    float acc[8][4];
#pragma unroll
    for (int i = 0; i < 8; i++)
#pragma unroll
        for (int j = 0; j < 4; j++) acc[i][j] = 0.f;

    for (int k0 = 0; k0 < OP::KD; k0 += 16){
#pragma unroll
        for (int i = 0; i < 4; i++){
            int idx = t + i*256;
            int rr = idx >> 4, kk = idx & 15;
            int row = row0 + rr;
            As[kk*65 + rr] = (row < OP::ROWS) ? op.loadA(z, row, k0 + kk) : 0.f;
        }
#pragma unroll
        for (int i = 0; i < 8; i++){
            int idx = t + i*256;
            int kk = idx >> 7, nn = idx & 127;
            Bs[kk*128 + nn] = op.loadB(z, k0 + kk, col0 + nn);
        }
        __syncthreads();
#pragma unroll
        for (int kk = 0; kk < 16; kk++){
            float4 b = *(const float4*)&Bs[kk*128 + tc*4];
            float a[8];
#pragma unroll
            for (int i = 0; i < 8; i++) a[i] = As[kk*65 + tr*8 + i];
#pragma unroll
            for (int i = 0; i < 8; i++){
                acc[i][0] += a[i]*b.x;
                acc[i][1] += a[i]*b.y;
                acc[i][2] += a[i]*b.z;
                acc[i][3] += a[i]*b.w;
            }
        }
        __syncthreads();
    }
#pragma unroll
    for (int i = 0; i < 8; i++){
        int row = row0 + tr*8 + i;
        if (row >= OP::ROWS) continue;
#pragma unroll
        for (int j = 0; j < 4; j++) op.store(z, row, col0 + tc*4 + j, acc[i][j]);
    }
    __syncthreads();
}

template <class OP>
__device__ void tile_gemm64(const OP& op, int row0, int col0, int z, float* sh, int t){
    float* As = sh;
    float* Bs = sh + 1040;
    const int tr = t >> 5, tc = t & 31;
    float acc[8][2];
#pragma unroll
    for (int i = 0; i < 8; i++){ acc[i][0] = 0.f; acc[i][1] = 0.f; }

    for (int k0 = 0; k0 < OP::KD; k0 += 16){
#pragma unroll
        for (int i = 0; i < 4; i++){
            int idx = t + i*256;
            int rr = idx >> 4, kk = idx & 15;
            int row = row0 + rr;
            As[kk*65 + rr] = (row < OP::ROWS) ? op.loadA(z, row, k0 + kk) : 0.f;
        }
#pragma unroll
        for (int i = 0; i < 4; i++){
            int idx = t + i*256;
            int kk = idx >> 6, nn = idx & 63;
            Bs[kk*64 + nn] = op.loadB(z, k0 + kk, col0 + nn);
        }
        __syncthreads();
#pragma unroll
        for (int kk = 0; kk < 16; kk++){
            float2 b = *(const float2*)&Bs[kk*64 + tc*2];
            float a[8];
#pragma unroll
            for (int i = 0; i < 8; i++) a[i] = As[kk*65 + tr*8 + i];
#pragma unroll
            for (int i = 0; i < 8; i++){
                acc[i][0] += a[i]*b.x;
                acc[i][1] += a[i]*b.y;
            }
        }
        __syncthreads();
    }
#pragma unroll
    for (int i = 0; i < 8; i++){
        int row = row0 + tr*8 + i;
        if (row >= OP::ROWS) continue;
        op.store(z, row, col0 + tc*2, acc[i][0]);
        op.store(z, row, col0 + tc*2 + 1, acc[i][1]);
    }
    __syncthreads();
}

__device__ void tile_transpose(const float* in, float* out, int R, int C,
                               int c0, int r0, float* sh, int t){
    float* tile = sh;
    int tx = t & 31, ty = t >> 5;
#pragma unroll
    for (int i = 0; i < 32; i += 8){
        int r = r0 + ty + i, c = c0 + tx;
        tile[(ty + i)*33 + tx] = (r < R && c < C) ? in[(long)r*C + c] : 0.f;
    }
    __syncthreads();
#pragma unroll
    for (int i = 0; i < 32; i += 8){
        int c = c0 + ty + i, r = r0 + tx;
        if (c < C && r < R) out[(long)c*R + r] = tile[tx*33 + ty + i];
    }
    __syncthreads();
}

__device__ void tile_wal(const float* sent, const int* aidx, int bm, int t){
    int b = bm / Mn;
    int idx = aidx[bm];
    const float* src = sent + ((long)b*Nn + idx)*Hn;
#pragma unroll
    for (int i = 0; i < 2; i++) g_wal[bm*Hn + t + i*256] = src[t + i*256];
}

__device__ void tile_us(const float* Wt, const float* btr, const float* wsh,
                        const float* bsh, const float* wfin, int s, int t){
    int w = t >> 5, lane = t & 31;
    for (int h = w; h < Hn; h += 8){
        const float* wrow = Wt + ((long)s*Hn + h)*Hn;
        float aU = 0.f, aV = 0.f;
        for (int g = lane; g < Hn; g += 32){
            float x = wrow[g];
            aU += x*wsh[g];
            aV += x*wfin[g];
        }
        aU = wsum(aU); aV = wsum(aV);
        if (lane == 0){ g_us[s*Hn + h] = aU; g_vs[s*Hn + h] = aV; }
    }
    if (w == 0){
        float dU = 0.f, dV = 0.f;
        for (int h = lane; h < Hn; h += 32){
            float b = btr[s*Hn + h];
            dU += b*wsh[h];
            dV += b*wfin[h];
        }
        dU = wsum(dU); dV = wsum(dV);
        if (lane == 0){ g_ds[s] = dU + bsh[0]; g_es[s] = dV; }
    }
}

__device__ void tile_maskdetect(const unsigned char* m, float* sh, int t){
    int* si = (int*)sh;
    if (t == 0){ si[0] = 0; si[1] = 0; }
    __syncthreads();
    int c1 = 0, c2 = 0;
    for (int i = t; i < BMKn; i += 256){
        unsigned char v = m[i];
        if (v > 1) c2++;
        else if (v == 1 && (i & 3)) c1++;
    }
    atomicAdd(&si[0], c1);
    atomicAdd(&si[1], c2);
    __syncthreads();
    if (t == 0) g_mask_mode = (si[1] > 0) ? 2 : ((si[0] > 0) ? 0 : 1);
    __syncthreads();
}

__device__ void tile_predg(const float* ctx, float* pred, int row0, float* sh, int t){
    for (int i = t; i < 5120; i += 256)
        sh[i] = (i < 2560) ? g_us[i] : g_vs[i - 2560];
    __syncthreads();
    int w = t >> 5, lane = t & 31;
    int rbase = row0 + w*32;
#pragma unroll 1
    for (int i = 0; i < 32; i++){
        int r = rbase + i;
        const float* cp = ctx + (long)r*Hn;
        float a[16];
#pragma unroll
        for (int j = 0; j < 16; j++) a[j] = cp[lane + 32*j];
#pragma unroll
        for (int d = 0; d < 10; d++){
            const float* vv = sh + d*512;
            float acc = 0.f;
#pragma unroll
            for (int j = 0; j < 16; j++) acc += a[j]*vv[lane + 32*j];
            acc = wsum(acc);
            if (lane == 0){
                if (d < Sn) pred[r*Sn + d] = acc + g_ds[d];
                else        g_fdot[r*Sn + (d - Sn)] = acc + g_es[d - Sn];
            }
        }
    }
    __syncthreads();
}

__device__ void tile_margin(const float* pred, const void* mask, int bm, int t){
    int w = t >> 5, k = t & 31;
    if (w >= Sn) return;
    bool act = (k < Kn);
    float logit = NEG_BIG;
    if (act){
        float pv = pred[(bm*Kn + k)*Sn + w];
        logit = mask_padded(mask, bm*Kn + k) ? NEG_BIG : pv;
    }
    float mx = wmaxf(act ? logit : NEG_INF);
    float e = act ? expf(logit - mx) : 0.f;
    float sm = wsum(e);
    float lse = logf(sm);
    float conf = act ? (logit - mx - lse) : NEG_INF;
    float v = conf; int idx = k;
#pragma unroll
    for (int o = 16; o; o >>= 1){
        float v2 = __shfl_xor_sync(0xffffffffu, v, o);
        int   i2 = __shfl_xor_sync(0xffffffffu, idx, o);
        if (v2 > v || (v2 == v && i2 < idx)){ v = v2; idx = i2; }
    }
    float c2 = (act && k != idx) ? conf : NEG_INF;
    float v2m = wmaxf(c2);
    if (k == 0) g_margin[bm*Sn + w] = (v - v2m) / (v + v2m);
}

__device__ void tile_sm1(int grp, int t){
    int w = t >> 5, lane = t & 31;
#pragma unroll
    for (int rr = 0; rr < 2; rr++){
        long row = (long)grp*16 + w + rr*8;
        float v[4]; float mx = NEG_INF;
#pragma unroll
        for (int i = 0; i < 4; i++){ v[i] = g_sc1[row*Nn + lane + 32*i]; mx = fmaxf(mx, v[i]); }
        mx = wmaxf(mx);
        float sm = 0.f;
#pragma unroll
        for (int i = 0; i < 4; i++){ v[i] = expf(v[i] - mx); sm += v[i]; }
        sm = wsum(sm);
        float inv = 1.f/sm;
#pragma unroll
        for (int i = 0; i < 4; i++) g_sc1[row*Nn + lane + 32*i] = v[i]*inv;
    }
}

// ---------------- persistent megakernel ----------------
__global__ __launch_bounds__(256, 4) void k_mega(
    const float* __restrict__ sent, const int* __restrict__ aidx,
    const void* __restrict__ mask, const float* __restrict__ ctx,
    const float* __restrict__ Wt, const float* __restrict__ btr,
    const float* __restrict__ wsh, const float* __restrict__ bsh,
    const float* __restrict__ wfin, const float* __restrict__ Wq,
    const float* __restrict__ Wv, const float* __restrict__ Wq2,
    const float* __restrict__ Wk, const float* __restrict__ Wk2,
    const float* __restrict__ sla, const float* __restrict__ sle,
    float* __restrict__ pred)
{
    __shared__ float sh[5200];
    const int t = threadIdx.x;
    const unsigned NB = gridDim.x;

    // S0
    for (unsigned tt = blockIdx.x; tt < 7302u; tt += NB){
        if (tt < 1280u){
            int cx = tt & 15, cy = (tt >> 4) & 15, z = tt >> 8;
            tile_transpose(Wk + (long)z*HH, g_WkT + (long)z*HH, Hn, Hn, cx*32, cy*32, sh, t);
        } else if (tt < 2560u){
            unsigned u = tt - 1280u;
            int cx = u & 15, cy = (u >> 4) & 15, z = u >> 8;
            tile_transpose(Wk2 + (long)z*HH, g_Wk2T + (long)z*HH, Hn, Hn, cx*32, cy*32, sh, t);
        } else if (tt < 6656u){
            unsigned u = tt - 2560u;
            int cx = u & 15, cy = (u >> 4) & 3, z = u >> 6;
            tile_transpose(sent + (long)z*Nn*Hn, g_sentT + (long)z*Hn*Nn, Nn, Hn, cx*32, cy*32, sh, t);
        } else if (tt < 7296u){
            tile_wal(sent, aidx, (int)(tt - 6656u), t);
        } else if (tt < 7301u){
            tile_us(Wt, btr, wsh, bsh, wfin, (int)(tt - 7296u), t);
        } else {
            tile_maskdetect((const unsigned char*)mask, sh, t);
        }
    }
    grid_barrier();

    // S1: predg (75) + Q1 (200)
    {
        OpQ1 op{Wq, sla};
        for (unsigned tt = blockIdx.x; tt < 275u; tt += NB){
            if (tt < 75u) tile_predg(ctx, pred, (int)tt*256, sh, t);
            else {
                unsigned q = tt - 75u;
                tile_gemm128(op, (int)(q % 10u)*64, (int)((q/10u) % 4u)*128, (int)(q/40u), sh, t);
            }
        }
    }
    grid_barrier();

    // S2: margin (640) + T (1600)
    {
        OpT op{};
        for (unsigned tt = blockIdx.x; tt < 2240u; tt += NB){
            if (tt < 640u) tile_margin(pred, mask, (int)tt, t);
            else {
                unsigned q = tt - 640u;
                tile_gemm128(op, (int)(q % 10u)*64, (int)((q/10u) % 4u)*128, (int)(q/40u), sh, t);
            }
        }
    }
    grid_barrier();

    // S3: SC1 (448)
    {
        OpSC1 op{};
        for (unsigned tt = blockIdx.x; tt < 448u; tt += NB)
            tile_gemm128(op, (int)(tt % 7u)*64, 0, (int)(tt/7u), sh, t);
    }
    grid_barrier();

    // S4: sm1
    for (unsigned tt = blockIdx.x; tt < 1600u; tt += NB) tile_sm1((int)tt, t);
    grid_barrier();

    // S5: U
    {
        OpU op{sent};
        for (unsigned tt = blockIdx.x; tt < 1792u; tt += NB)
            tile_gemm128(op, (int)(tt % 7u)*64, (int)((tt/7u) % 4u)*128, (int)(tt/28u), sh, t);
    }
    grid_barrier();

    // S6: CTX1
    {
        OpCTX1 op{Wv};
        for (unsigned tt = blockIdx.x; tt < 400u; tt += NB)
            tile_gemm64(op, (int)(tt % 10u)*64, 0, (int)(tt/10u), sh, t);
    }
    grid_barrier();

    // S7: Q2
    {
        OpQ2 op{Wq2, sle};
        for (unsigned tt = blockIdx.x; tt < 200u; tt += NB)
            tile_gemm128(op, (int)(tt % 10u)*64, (int)((tt/10u) % 4u)*128, (int)(tt/40u), sh, t);
    }
    grid_barrier();

    // S8: R
    {
        OpR op{};
        for (unsigned tt = blockIdx.x; tt < 1600u; tt += NB)
            tile_gemm128(op, (int)(tt % 10u)*64, (int)((tt/10u) % 4u)*128, (int)(tt/40u), sh, t);
    }
}

// ---------------- stage2 (CP=524: conflict-free LDS.128 rows) ----------------
#define CP 524
__global__ void k_stage2(const float* __restrict__ ctx, const void* __restrict__ mask,
                         const float* __restrict__ Wind, const float* __restrict__ bind,
                         float* __restrict__ ind_out){
    extern __shared__ float smem[];
    float* ctx_sh   = smem;
    float* r_sh     = ctx_sh + Kn*CP;
    float* alias_sh = r_sh + NHn*CP;
    float* ew_sh    = alias_sh + Hn;
    float* red      = ew_sh + NHn*32;

    int blk = blockIdx.x;
    int m = blk % Mn; int bs = blk / Mn; int s = bs % Sn; int b = bs / Sn;
    int bm = b*Mn + m;
    int tid = threadIdx.x;
    for (int i = tid; i < Kn*Hn; i += 256){
        int r = i >> 9, h = i & 511;
        ctx_sh[r*CP + h] = ctx[((long)bm*Kn + r)*Hn + h];
    }
    for (int i = tid; i < NHn*Hn; i += 256){
        int a = i >> 9, h = i & 511;
        r_sh[a*CP + h] = g_r[((long)blk*NHn + a)*Hn + h];
    }
    __syncthreads();

    int a = tid >> 5, k = tid & 31;
    {
        bool act = (k < Kn);
        float acc = 0.f;
        if (act){
            const float4* cp = reinterpret_cast<const float4*>(ctx_sh + k*CP);
            const float4* rp = reinterpret_cast<const float4*>(r_sh + a*CP);
            for (int h4 = 0; h4 < Hn/4; h4++){
                float4 c = cp[h4], rr = rp[h4];
                acc += c.x*rr.x + c.y*rr.y + c.z*rr.z + c.w*rr.w;
            }
        }
        float x = NEG_BIG;
        if (act) x = mask_padded(mask, bm*Kn + k) ? NEG_BIG : acc*0.125f;
        float mx = wmaxf(act ? x : NEG_INF);
        float e = act ? expf(x - mx) : 0.f;
        float sv = wsum(e);
        if (act) ew_sh[a*32 + k] = e/sv;
    }
    __syncthreads();
    for (int g = tid; g < Hn; g += 256){
        int ah = g >> 6;
        float acc = 0.f;
#pragma unroll
        for (int kk = 0; kk < Kn; kk++) acc += ew_sh[ah*32 + kk]*ctx_sh[kk*CP + g];
        alias_sh[g] = acc;
    }
    __syncthreads();
    float p0 = 0.f, p1 = 0.f;
    for (int g = tid; g < Hn; g += 256){
        float av = alias_sh[g];
        p0 += av*Wind[(s*Hn + g)*2 + 0];
        p1 += av*Wind[(s*Hn + g)*2 + 1];
    }
    p0 = wsum(p0); p1 = wsum(p1);
    if ((tid & 31) == 0){ red[(tid >> 5)*2] = p0; red[(tid >> 5)*2 + 1] = p1; }
    __syncthreads();
    if (tid == 0){
        float i0 = 0.f, i1 = 0.f;
        for (int wv = 0; wv < 8; wv++){ i0 += red[wv*2]; i1 += red[wv*2 + 1]; }
        i0 += bind[s*2 + 0]; i1 += bind[s*2 + 1];
        ind_out[blk*2 + 0] = i0;
        ind_out[blk*2 + 1] = i1;
        float mx = fmaxf(i0, i1);
        float lse = mx + logf(expf(i0 - mx) + expf(i1 - mx));
        g_indp[bm*Sn + s] = i1 - lse;
    }
}

__global__ void k_attn_beff(const float* __restrict__ btr){
    __shared__ float at[Sn];
    int bm = blockIdx.x, t = threadIdx.x;
    if (t < 32){
        int s = t;
        bool act = (s < Sn);
        float x = act ? (g_indp[bm*Sn + s] + g_margin[bm*Sn + s])*4.0f : NEG_INF;
        float mx = wmaxf(x);
        float e = act ? expf(x - mx) : 0.f;
        float sm = wsum(e);
        if (act){ float v = e/sm; g_attn[bm*Sn + s] = v; at[s] = v; }
    }
    __syncthreads();
    float acc = 0.f;
#pragma unroll
    for (int s = 0; s < Sn; s++) acc += at[s]*btr[s*Hn + t];
    g_beff[bm*Hn + t] = acc;
}

__global__ void k_finalv(const float* __restrict__ bfin, float* __restrict__ out){
    int i = blockIdx.x*256 + threadIdx.x;
    if (i >= BMKn) return;
    int bm = i / Kn;
    float acc = bfin[0];
#pragma unroll
    for (int s = 0; s < Sn; s++) acc += g_attn[bm*Sn + s]*g_fdot[i*Sn + s];
    out[i] = acc;
}

// ---------------- REW phase 1: Weff in fp16, tile-blocked (R16 measured-best) ------
__global__ __launch_bounds__(256) void k_weff(const float* __restrict__ Wt){
    __shared__ float at[BMn*Sn];
    const int kt = blockIdx.x, nt = blockIdx.y;
    const int k0 = kt*32, n0 = nt*64;
    const int t = threadIdx.x;
    for (int i = t; i < BMn*Sn; i += 256) at[i] = g_attn[i];
    const int kk = t >> 3, cg = t & 7;
    float w[Sn][8];
#pragma unroll
    for (int s = 0; s < Sn; s++){
        *(float4*)&w[s][0] = *(const float4*)&Wt[((long)s*Hn + k0 + kk)*Hn + n0 + cg*8];
        *(float4*)&w[s][4] = *(const float4*)&Wt[((long)s*Hn + k0 + kk)*Hn + n0 + cg*8 + 4];
    }
    __syncthreads();
    __half* dst0 = g_weffh + ((long)(kt*8 + nt)*BMn)*2048 + kk*64 + cg*8;
    for (int bm = 0; bm < BMn; bm++){
        float a0 = at[bm*Sn+0], a1 = at[bm*Sn+1], a2 = at[bm*Sn+2],
              a3 = at[bm*Sn+3], a4 = at[bm*Sn+4];
        __half2 o[4];
#pragma unroll
        for (int j = 0; j < 4; j++){
            float v0 = a0*w[0][2*j]   + a1*w[1][2*j]   + a2*w[2][2*j]
                     + a3*w[3][2*j]   + a4*w[4][2*j];
            float v1 = a0*w[0][2*j+1] + a1*w[1][2*j+1] + a2*w[2][2*j+1]
                     + a3*w[3][2*j+1] + a4*w[4][2*j+1];
            o[j] = __floats2half2_rn(v0, v1);
        }
        *(uint4*)(dst0 + (long)bm*2048) = *(uint4*)o;
    }
}

// ---------------- REW phase 2: single-pass fp16 tensor-core GEMM ----------------
// One block per bm: M=32 (30 valid), N=512, K=512. 8 warps, warp w -> cols [w*64,+64).
// k-chunk 16 (m16n8k16). A: ctx converted to fp16 in-kernel; B: fp16 from g_weffh.
// Fragment layout identical to R9's verified bf16 path (k-pairs packed, even k low).
__global__ __launch_bounds__(256) void k_rewH(const float* __restrict__ ctx,
                                              float* __restrict__ outp){
    __shared__ unsigned Apk[8][40];    // [kpair][row] packed half2
    __shared__ unsigned Bpk[8][520];   // [kpair][col] packed half2

    const int bm = blockIdx.x;
    const int t = threadIdx.x;
    const int w = t >> 5, lane = t & 31;

    const float* A = ctx + (long)bm*Kn*Hn;

    float d[2][8][4];
#pragma unroll
    for (int m = 0; m < 2; m++)
#pragma unroll
        for (int nt = 0; nt < 8; nt++)
#pragma unroll
            for (int r = 0; r < 4; r++) d[m][nt][r] = 0.f;

    const int akp = t >> 5, ar = t & 31;

    for (int k0 = 0; k0 < Hn; k0 += 16){
        const int kt = k0 >> 5;
        const int kin0 = k0 & 31;
        // A: 32 rows x 8 kpairs, one per thread, pack fp32->half2
        {
            float x0 = 0.f, x1 = 0.f;
            if (ar < Kn){
                x0 = A[ar*Hn + k0 + 2*akp];
                x1 = A[ar*Hn + k0 + 2*akp + 1];
            }
            __half2 h = __floats2half2_rn(x0, x1);
            Apk[akp][ar] = *(unsigned*)&h;
        }
        // B: 8 kpairs x 512 cols from fp16 blocked weff; interleave adjacent k rows.
        // 512 slots of 8 cols each -> 2 per thread.
#pragma unroll
        for (int p = 0; p < 2; p++){
            int idx = t + p*256;           // 0..511
            int kp = idx >> 6;             // 0..7
            int c8 = (idx & 63)*8;         // 0..504
            int nt = c8 >> 6, cin = c8 & 63;
            const __half* base = g_weffh + ((long)(kt*8 + nt)*BMn + bm)*2048
                               + (kin0 + 2*kp)*64 + cin;
            uint4 r0 = *(const uint4*)base;          // k even row, 8 halves
            uint4 r1 = *(const uint4*)(base + 64);   // k odd row, 8 halves
            const __half* e = (const __half*)&r0;
            const __half* o = (const __half*)&r1;
            unsigned outp8[8];
#pragma unroll
            for (int j = 0; j < 8; j++){
                __half2 h = __halves2half2(e[j], o[j]);
                outp8[j] = *(unsigned*)&h;
            }
            *(uint4*)&Bpk[kp][c8]     = *(uint4*)&outp8[0];
            *(uint4*)&Bpk[kp][c8 + 4] = *(uint4*)&outp8[4];
        }
        __syncthreads();

        // A fragments (m16n8k16 row-major): r=lane>>2, kpair c=lane&3
        const int fr = lane >> 2, fc = lane & 3;
        unsigned af[2][4];
#pragma unroll
        for (int m = 0; m < 2; m++){
            int rb = fr + m*16;
            af[m][0] = Apk[fc][rb];
            af[m][1] = Apk[fc][rb + 8];
            af[m][2] = Apk[fc + 4][rb];
            af[m][3] = Apk[fc + 4][rb + 8];
        }
#pragma unroll
        for (int nt = 0; nt < 8; nt++){
            int bn = w*64 + nt*8 + (lane >> 2);
            unsigned b0 = Bpk[fc][bn];
            unsigned b1 = Bpk[fc + 4][bn];
#pragma unroll
            for (int m = 0; m < 2; m++)
                mma_f16(d[m][nt], af[m][0], af[m][1], af[m][2], af[m][3], b0, b1);
        }
        __syncthreads();
    }

    // epilogue: D layout c0=(r, 2c) c1=(r, 2c+1) c2=(r+8, 2c) c3=(r+8, 2c+1)
    const int er = lane >> 2, ec = (lane & 3)*2;
#pragma unroll
    for (int nt = 0; nt < 8; nt++){
        int col = w*64 + nt*8 + ec;
        float2 be = *(const float2*)&g_beff[bm*Hn + col];
#pragma unroll
        for (int m = 0; m < 2; m++){
            int r0 = er + m*16;
            int r1 = r0 + 8;
            if (r0 < Kn){
                float2 v = {d[m][nt][0] + be.x, d[m][nt][1] + be.y};
                *(float2*)&outp[((long)(bm*Kn + r0))*Hn + col] = v;
            }
            if (r1 < Kn){
                float2 v = {d[m][nt][2] + be.x, d[m][nt][3] + be.y};
                *(float2*)&outp[((long)(bm*Kn + r1))*Hn + col] = v;
            }
        }
    }
}

// ---------------- host launcher ----------------
extern "C" void kernel_launch(void* const* d_in, const int* in_sizes, int n_in,
                              void* d_out, int out_size){
    const float* ctx  = (const float*)d_in[0];
    const float* sent = (const float*)d_in[1];
    const int*   aidx = (const int*)d_in[2];
    const void*  mask = (const void*)d_in[3];
    const float* Wtr  = (const float*)d_in[4];
    const float* btr  = (const float*)d_in[5];
    const float* Wind = (const float*)d_in[6];
    const float* bind = (const float*)d_in[7];
    const float* Wq   = (const float*)d_in[8];
    const float* Wk   = (const float*)d_in[9];
    const float* Wv   = (const float*)d_in[10];
    const float* Wq2  = (const float*)d_in[11];
    const float* Wk2  = (const float*)d_in[12];
    const float* sla  = (const float*)d_in[13];
    const float* sle  = (const float*)d_in[14];
    const float* wsh  = (const float*)d_in[15];
    const float* bsh  = (const float*)d_in[16];
    const float* wfin = (const float*)d_in[17];
    const float* bfin = (const float*)d_in[18];
    float* out = (float*)d_out;

    void* tmp;
    cudaGetSymbolAddress(&tmp, g_pred_s); float* pred_s = (float*)tmp;
    cudaGetSymbolAddress(&tmp, g_ind_s);  float* ind_s  = (float*)tmp;

    const bool big_out = (out_size >= (BMKn + BMKn*Hn + BMKn*Sn + Bn*Sn*Mn*2));
    float *p_final = out;
    float *p_rew  = big_out ? out + BMKn : nullptr;
    float *p_pred = big_out ? out + BMKn + BMKn*Hn : pred_s;
    float *p_ind  = big_out ? out + BMKn + BMKn*Hn + BMKn*Sn : ind_s;

    cudaFuncSetAttribute(k_stage2, cudaFuncAttributeMaxDynamicSharedMemorySize, 90*1024);

    int dev = 0; cudaGetDevice(&dev);
    int sms = 148;
    cudaDeviceGetAttribute(&sms, cudaDevAttrMultiProcessorCount, dev);
    int nb = 0;
    cudaOccupancyMaxActiveBlocksPerMultiprocessor(&nb, k_mega, 256, 0);
    if (nb < 4) nb = 4;
    int grid = nb * sms;

    k_mega<<<grid, 256>>>(sent, aidx, mask, ctx, Wtr, btr, wsh, bsh, wfin,
                          Wq, Wv, Wq2, Wk, Wk2, sla, sle, p_pred);

    size_t sm2 = (size_t)(Kn*CP + NHn*CP + Hn + NHn*32 + 16)*sizeof(float);
    k_stage2<<<Bn*Sn*Mn, 256, sm2>>>(ctx, mask, Wind, bind, p_ind);

    k_attn_beff<<<BMn, 512>>>(btr);

    if (big_out){
        k_weff<<<dim3(16, 8), 256>>>(Wtr);
        k_rewH<<<BMn, 256>>>(ctx, p_rew);
    }
    k_finalv<<<(BMKn + 255)/256, 256>>>(bfin, p_final);
}